// round 3
// baseline (speedup 1.0000x reference)
#include <cuda_runtime.h>
#include <cstdint>

#define TPB 256

// B=4, U=64, V=256, DIM=768, CODE=384, INNER=512, HEADS=8, HD=64

struct Params {
    const float *recv, *codes, *send;
    const float *lnrg, *lnrb, *lnsg, *lnsb;
    const float *Wq, *bq, *Wmq, *Wk, *bk, *Wmk;
    const float *Wv, *bv, *Wmv, *We, *be, *Wme, *gamma;
    float* out;
    int nb;
};

// ---------------- Scratch (device globals; no allocs) ----------------
__device__ float g_r  [256 * 768];
__device__ float g_s  [1024 * 768];
__device__ float g_mq [256 * 768];
__device__ float g_mk [256 * 768];
__device__ float g_mv [256 * 768];
__device__ float g_me [256 * 512];
__device__ float g_q  [256 * 512];
__device__ float g_qbk[256 * 8];
__device__ float g_Ak [4 * 512 * 768];
__device__ float g_w  [4 * 512 * 256];
__device__ float g_Tm [8 * 256 * 768];
__device__ float g_msg[256 * 512];

__device__ unsigned g_barcnt = 0;
__device__ unsigned g_bargen = 0;

// Software grid barrier (grid == resident-block count).
__device__ __forceinline__ void grid_bar(int nb) {
    __syncthreads();
    if (threadIdx.x == 0) {
        __threadfence();
        unsigned gen = *(volatile unsigned*)&g_bargen;
        unsigned t = atomicAdd(&g_barcnt, 1u);
        if (t == (unsigned)(nb - 1)) {
            atomicExch(&g_barcnt, 0u);
            __threadfence();
            atomicExch(&g_bargen, gen + 1u);
        } else {
            while (*(volatile unsigned*)&g_bargen == gen) { __nanosleep(32); }
        }
        __threadfence();
    }
    __syncthreads();
}

// ---------------- tf32 helpers ----------------
__device__ __forceinline__ uint32_t f2tf(float x) {
    uint32_t u;
    asm("cvt.rna.tf32.f32 %0, %1;" : "=r"(u) : "f"(x));
    return u;
}

__device__ __forceinline__ void mma8(float* c, const uint32_t* a, const uint32_t* b) {
    asm volatile(
        "mma.sync.aligned.m16n8k8.row.col.f32.tf32.tf32.f32 "
        "{%0,%1,%2,%3}, {%4,%5,%6,%7}, {%8,%9}, {%0,%1,%2,%3};"
        : "+f"(c[0]), "+f"(c[1]), "+f"(c[2]), "+f"(c[3])
        : "r"(a[0]), "r"(a[1]), "r"(a[2]), "r"(a[3]), "r"(b[0]), "r"(b[1]));
}

// ---------------- per-warp 32x32 tf32 GEMM tile (no smem, no syncs) ----
// C[m,n] = sum_k A(m,k)*B(k,n); K % 8 == 0.
template<class AL, class BL, class EP>
__device__ __forceinline__ void wtile32(int K, AL la, BL lb, EP ep) {
    const int l = threadIdx.x & 31;
    const int g = l >> 2, t = l & 3;
    float acc[2][4][4];
    #pragma unroll
    for (int i = 0; i < 2; i++)
        #pragma unroll
        for (int j = 0; j < 4; j++)
            #pragma unroll
            for (int e = 0; e < 4; e++) acc[i][j][e] = 0.f;

    #pragma unroll 2
    for (int k0 = 0; k0 < K; k0 += 8) {
        uint32_t A[2][4], Bf[4][2];
        #pragma unroll
        for (int i = 0; i < 2; i++) {
            int r0 = 16 * i + g, r1 = r0 + 8;
            A[i][0] = f2tf(la(r0, k0 + t));
            A[i][1] = f2tf(la(r1, k0 + t));
            A[i][2] = f2tf(la(r0, k0 + t + 4));
            A[i][3] = f2tf(la(r1, k0 + t + 4));
        }
        #pragma unroll
        for (int j = 0; j < 4; j++) {
            int n = 8 * j + g;
            Bf[j][0] = f2tf(lb(k0 + t, n));
            Bf[j][1] = f2tf(lb(k0 + t + 4, n));
        }
        #pragma unroll
        for (int i = 0; i < 2; i++)
            #pragma unroll
            for (int j = 0; j < 4; j++)
                mma8(acc[i][j], A[i], Bf[j]);
    }
    #pragma unroll
    for (int i = 0; i < 2; i++)
        #pragma unroll
        for (int j = 0; j < 4; j++) {
            int r = 16 * i + g, c = 8 * j + 2 * t;
            ep(r,     c,     acc[i][j][0]);
            ep(r,     c + 1, acc[i][j][1]);
            ep(r + 8, c,     acc[i][j][2]);
            ep(r + 8, c + 1, acc[i][j][3]);
        }
}

// ---------------- warp LayerNorm over a 768-row ----------------
__device__ __forceinline__ void ln_row(const float* __restrict__ x,
                                       const float* __restrict__ g,
                                       const float* __restrict__ b,
                                       float* __restrict__ o) {
    int lane = threadIdx.x & 31;
    float v[24];
    float s = 0.f, q = 0.f;
    #pragma unroll
    for (int i = 0; i < 24; i++) {
        v[i] = x[lane + 32 * i];
        s += v[i];
        q += v[i] * v[i];
    }
    #pragma unroll
    for (int off = 16; off; off >>= 1) {
        s += __shfl_xor_sync(0xffffffffu, s, off);
        q += __shfl_xor_sync(0xffffffffu, q, off);
    }
    float mu  = s * (1.f / 768.f);
    float inv = rsqrtf(q * (1.f / 768.f) - mu * mu + 1e-5f);
    #pragma unroll
    for (int i = 0; i < 24; i++) {
        int idx = lane + 32 * i;
        o[idx] = (v[i] - mu) * inv * g[idx] + b[idx];
    }
}

// ---------------- The single persistent kernel ----------------
__global__ void __launch_bounds__(TPB, 2) fused_kernel(Params P) {
    const int nb = P.nb;
    const int wglob = blockIdx.x * (TPB / 32) + (threadIdx.x >> 5);
    const int nwarp = nb * (TPB / 32);
    const int lane32 = threadIdx.x & 31;

    // ---- Stage 1: LayerNorms + 4 modulation GEMMs (all depend only on inputs) ----
    for (int r = wglob; r < 1280; r += nwarp) {
        if (r < 256) ln_row(P.recv + r * 768, P.lnrg, P.lnrb, g_r + r * 768);
        else {
            int rr = r - 256;
            ln_row(P.send + rr * 768, P.lnsg, P.lnsb, g_s + rr * 768);
        }
    }
    for (int tt = wglob; tt < 704; tt += nwarp) {
        const float* W; float* O; int N; int lt;
        if (tt < 192)      { W = P.Wmq; O = g_mq; N = 768; lt = tt; }
        else if (tt < 384) { W = P.Wmk; O = g_mk; N = 768; lt = tt - 192; }
        else if (tt < 576) { W = P.Wmv; O = g_mv; N = 768; lt = tt - 384; }
        else               { W = P.Wme; O = g_me; N = 512; lt = tt - 576; }
        int m0 = (lt & 7) * 32, n0 = (lt >> 3) * 32;
        wtile32(384,
            [&](int m, int k) { return P.codes[(m0 + m) * 384 + k]; },
            [&](int k, int n) { return W[k * N + n0 + n]; },
            [&](int m, int n, float a) { O[(m0 + m) * N + n0 + n] = a; });
    }
    grid_bar(nb);

    // ---- Stage 2: q = (r*(1+mq)) @ Wq + bq   [256,768]x[768,512] ----
    for (int tt = wglob; tt < 128; tt += nwarp) {
        int m0 = (tt & 7) * 32, n0 = (tt >> 3) * 32;
        wtile32(768,
            [&](int m, int k) { int i = (m0 + m) * 768 + k; return g_r[i] * (1.f + g_mq[i]); },
            [&](int k, int n) { return P.Wq[k * 512 + n0 + n]; },
            [&](int m, int n, float a) { g_q[(m0 + m) * 512 + n0 + n] = a + P.bq[n0 + n]; });
    }
    grid_bar(nb);

    // ---- Stage 3: qbk dots + Ak = (Wk_h^T q_h)*(1+mk)  per-head NT, K=64 ----
    for (int w = wglob; w < 2048; w += nwarp) {
        int bu = w >> 3, h = w & 7;
        const float* qp = g_q + bu * 512 + h * 64;
        const float* bp = P.bk + h * 64;
        float s = qp[lane32] * bp[lane32] + qp[lane32 + 32] * bp[lane32 + 32];
        #pragma unroll
        for (int off = 16; off; off >>= 1) s += __shfl_xor_sync(0xffffffffu, s, off);
        if (lane32 == 0) g_qbk[bu * 8 + h] = s;
    }
    for (int tt = wglob; tt < 1536; tt += nwarp) {
        int h = tt / 192, lt = tt % 192;
        int m0 = (lt & 7) * 32, n0 = (lt >> 3) * 32;
        wtile32(64,
            [&](int m, int k) { return g_q[(m0 + m) * 512 + h * 64 + k]; },
            [&](int k, int n) { return P.Wk[(n0 + n) * 512 + h * 64 + k]; },
            [&](int m, int n, float a) {
                int mg = m0 + m; int b = mg >> 6, u = mg & 63;
                g_Ak[b * 393216 + (h * 64 + u) * 768 + n0 + n] =
                    a * (1.f + g_mk[mg * 768 + n0 + n]);
            });
    }
    grid_bar(nb);

    // ---- Stage 4: scores = (Ak @ s^T + qbk)/8   per-batch NT, K=768 ----
    for (int tt = wglob; tt < 512; tt += nwarp) {
        int b = tt >> 7, lt = tt & 127;
        int m0 = (lt & 15) * 32, n0 = (lt >> 4) * 32;
        wtile32(768,
            [&](int m, int k) { return g_Ak[b * 393216 + (m0 + m) * 768 + k]; },
            [&](int k, int n) { return g_s[(b * 256 + n0 + n) * 768 + k]; },
            [&](int m, int n, float a) {
                int mg = m0 + m; int h = mg >> 6, u = mg & 63;
                g_w[b * 131072 + mg * 256 + n0 + n] =
                    (a + g_qbk[(b * 64 + u) * 8 + h]) * 0.125f;
            });
    }
    grid_bar(nb);

    // ---- Stage 5: softmax over v (2048 rows of 256) ----
    for (int r = wglob; r < 2048; r += nwarp) {
        float* p = g_w + r * 256;
        float v[8], mx = -1e30f;
        #pragma unroll
        for (int i = 0; i < 8; i++) { v[i] = p[lane32 + 32 * i]; mx = fmaxf(mx, v[i]); }
        #pragma unroll
        for (int off = 16; off; off >>= 1) mx = fmaxf(mx, __shfl_xor_sync(0xffffffffu, mx, off));
        float sm = 0.f;
        #pragma unroll
        for (int i = 0; i < 8; i++) { v[i] = expf(v[i] - mx); sm += v[i]; }
        #pragma unroll
        for (int off = 16; off; off >>= 1) sm += __shfl_xor_sync(0xffffffffu, sm, off);
        float inv = 1.f / sm;
        #pragma unroll
        for (int i = 0; i < 8; i++) p[lane32 + 32 * i] = v[i] * inv;
    }
    grid_bar(nb);

    // ---- Stage 6: Tm = (w @ s)*(1+mv), per-head remap   per-batch NN, K=256 ----
    for (int tt = wglob; tt < 1536; tt += nwarp) {
        int b = tt / 384, lt = tt % 384;
        int m0 = (lt & 15) * 32, n0 = (lt >> 4) * 32;
        wtile32(256,
            [&](int m, int k) { return g_w[b * 131072 + (m0 + m) * 256 + k]; },
            [&](int k, int n) { return g_s[(b * 256 + k) * 768 + n0 + n]; },
            [&](int m, int n, float a) {
                int mg = m0 + m; int h = mg >> 6, u = mg & 63; int bu = b * 64 + u;
                g_Tm[(h * 256 + bu) * 768 + n0 + n] = a * (1.f + g_mv[bu * 768 + n0 + n]);
            });
    }
    grid_bar(nb);

    // ---- Stage 7: msg = (Tm_h @ Wv_h + bv)*(1+me)   per-head NN, K=768 ----
    for (int tt = wglob; tt < 128; tt += nwarp) {
        int h = tt >> 4, lt = tt & 15;
        int m0 = (lt & 7) * 32, n0 = (lt >> 3) * 32;
        wtile32(768,
            [&](int m, int k) { return g_Tm[(h * 256 + m0 + m) * 768 + k]; },
            [&](int k, int n) { return P.Wv[k * 512 + h * 64 + n0 + n]; },
            [&](int m, int n, float a) {
                int c = h * 64 + n0 + n; int mg = m0 + m;
                g_msg[mg * 512 + c] = (a + P.bv[c]) * (1.f + g_me[mg * 512 + c]);
            });
    }
    grid_bar(nb);

    // ---- Stage 8: out = recv + (msg @ We + be)*gamma   [256,512]x[512,768] ----
    for (int tt = wglob; tt < 192; tt += nwarp) {
        int m0 = (tt & 7) * 32, n0 = (tt >> 3) * 32;
        wtile32(512,
            [&](int m, int k) { return g_msg[(m0 + m) * 512 + k]; },
            [&](int k, int n) { return P.We[k * 768 + n0 + n]; },
            [&](int m, int n, float a) {
                int mg = m0 + m, c = n0 + n;
                P.out[mg * 768 + c] = P.recv[mg * 768 + c] + (a + P.be[c]) * P.gamma[c];
            });
    }
}

// ---------------- Host launcher ----------------
extern "C" void kernel_launch(void* const* d_in, const int* in_sizes, int n_in,
                              void* d_out, int out_size) {
    (void)in_sizes; (void)n_in; (void)out_size;
    Params P;
    P.recv  = (const float*)d_in[0];
    P.codes = (const float*)d_in[1];
    P.send  = (const float*)d_in[2];
    P.lnrg  = (const float*)d_in[3];
    P.lnrb  = (const float*)d_in[4];
    P.lnsg  = (const float*)d_in[5];
    P.lnsb  = (const float*)d_in[6];
    P.Wq  = (const float*)d_in[7];
    P.bq  = (const float*)d_in[8];
    P.Wmq = (const float*)d_in[9];
    P.Wk  = (const float*)d_in[10];
    P.bk  = (const float*)d_in[11];
    P.Wmk = (const float*)d_in[12];
    P.Wv  = (const float*)d_in[13];
    P.bv  = (const float*)d_in[14];
    P.Wmv = (const float*)d_in[15];
    P.We  = (const float*)d_in[16];
    P.be  = (const float*)d_in[17];
    P.Wme = (const float*)d_in[18];
    P.gamma = (const float*)d_in[19];
    P.out = (float*)d_out;

    int occ = 0;
    cudaOccupancyMaxActiveBlocksPerMultiprocessor(&occ, fused_kernel, TPB, 0);
    if (occ < 1) occ = 1;
    int dev = 0;
    cudaGetDevice(&dev);
    int sms = 0;
    cudaDeviceGetAttribute(&sms, cudaDevAttrMultiProcessorCount, dev);
    if (sms < 1) sms = 1;
    int nb = occ * sms;
    if (nb > 1536) nb = 1536;
    P.nb = nb;

    fused_kernel<<<nb, TPB>>>(P);
}

// round 4
// speedup vs baseline: 1.8507x; 1.8507x over previous
#include <cuda_runtime.h>
#include <cstdint>

#define TPB 256

// B=4, U=64, V=256, DIM=768, CODE=384, INNER=512, HEADS=8, HD=64

struct Params {
    const float *recv, *codes, *send;
    const float *lnrg, *lnrb, *lnsg, *lnsb;
    const float *Wq, *bq, *Wmq, *Wk, *bk, *Wmk;
    const float *Wv, *bv, *Wmv, *We, *be, *Wme, *gamma;
    float* out;
    int nb;
};

// ---------------- Scratch (device globals; no allocs) ----------------
__device__ __align__(16) float g_r  [256 * 768];
__device__ __align__(16) float g_s  [1024 * 768];
__device__ __align__(16) float g_mq [256 * 768];
__device__ __align__(16) float g_mk [256 * 768];
__device__ __align__(16) float g_mv [256 * 768];
__device__ __align__(16) float g_me [256 * 512];
__device__ __align__(16) float g_q  [256 * 512];
__device__ __align__(16) float g_qbk[256 * 8];
__device__ __align__(16) float g_Ak [4 * 512 * 768];
__device__ __align__(16) float g_w  [4 * 512 * 256];
__device__ __align__(16) float g_Tm [8 * 256 * 768];
__device__ __align__(16) float g_msg[256 * 512];

__device__ unsigned g_barcnt = 0;
__device__ unsigned g_bargen = 0;

__device__ __forceinline__ void grid_bar(int nb) {
    __syncthreads();
    if (threadIdx.x == 0) {
        __threadfence();
        unsigned gen = *(volatile unsigned*)&g_bargen;
        unsigned t = atomicAdd(&g_barcnt, 1u);
        if (t == (unsigned)(nb - 1)) {
            atomicExch(&g_barcnt, 0u);
            __threadfence();
            atomicExch(&g_bargen, gen + 1u);
        } else {
            while (*(volatile unsigned*)&g_bargen == gen) { __nanosleep(32); }
        }
        __threadfence();
    }
    __syncthreads();
}

// ---------------- tf32 helpers ----------------
__device__ __forceinline__ uint32_t f2tf(float x) {
    uint32_t u;
    asm("cvt.rna.tf32.f32 %0, %1;" : "=r"(u) : "f"(x));
    return u;
}
__device__ __forceinline__ void mma8(float* c, const uint32_t* a, const uint32_t* b) {
    asm volatile(
        "mma.sync.aligned.m16n8k8.row.col.f32.tf32.tf32.f32 "
        "{%0,%1,%2,%3}, {%4,%5,%6,%7}, {%8,%9}, {%0,%1,%2,%3};"
        : "+f"(c[0]), "+f"(c[1]), "+f"(c[2]), "+f"(c[3])
        : "r"(a[0]), "r"(a[1]), "r"(a[2]), "r"(a[3]), "r"(b[0]), "r"(b[1]));
}

// smem strides (in uint32): A is [m][k] (64 x 16 + pad4), B is [k][n] (16 x 64 + pad8)
#define SAS 20
#define SBS 72
#define ABUF (64 * SAS)   // 1280
#define BBUF (16 * SBS)   // 1152

// ---------------- block-level 64x64 tf32 GEMM, double-buffered smem ------
// C(m,n) = sum_k A(m,k) * B(k,n), K % 16 == 0 (K/16 even for all our stages).
// la4(m,k) -> float4 A(m, k..k+3)
// BT=false: lb4(k,n) -> float4 B(k, n..n+3) ; BT=true: lb4(n,k) -> float4 B(k..k+3, n)
template<bool BT, class LA, class LB, class EP>
__device__ __forceinline__ void gemm_block(int K, uint32_t* sA, uint32_t* sB,
                                           LA la4, LB lb4, EP ep) {
    const int tid = threadIdx.x;
    const int l = tid & 31, g = l >> 2, t = l & 3;
    const int wid = tid >> 5;
    const int wm0 = (wid & 1) * 32, wn0 = (wid >> 1) * 16;
    const int am = tid >> 2, ak = (tid & 3) * 4;     // A fill coords
    const int bk = tid >> 4, bn = (tid & 15) * 4;    // B fill (NN)
    const int btn = tid >> 2, btk = (tid & 3) * 4;   // B fill (NT)

    float acc[2][2][4];
    #pragma unroll
    for (int i = 0; i < 2; i++)
        #pragma unroll
        for (int j = 0; j < 2; j++)
            #pragma unroll
            for (int e = 0; e < 4; e++) acc[i][j][e] = 0.f;

    float4 ra = la4(am, ak);
    float4 rb = BT ? lb4(btn, btk) : lb4(bk, bn);

    auto sts = [&](int p, const float4& va, const float4& vb) {
        uint32_t* A = sA + p * ABUF;
        uint32_t* B = sB + p * BBUF;
        uint4 ca; ca.x = f2tf(va.x); ca.y = f2tf(va.y); ca.z = f2tf(va.z); ca.w = f2tf(va.w);
        *(uint4*)&A[am * SAS + ak] = ca;
        if (BT) {
            B[(btk + 0) * SBS + btn] = f2tf(vb.x);
            B[(btk + 1) * SBS + btn] = f2tf(vb.y);
            B[(btk + 2) * SBS + btn] = f2tf(vb.z);
            B[(btk + 3) * SBS + btn] = f2tf(vb.w);
        } else {
            uint4 cb; cb.x = f2tf(vb.x); cb.y = f2tf(vb.y); cb.z = f2tf(vb.z); cb.w = f2tf(vb.w);
            *(uint4*)&B[bk * SBS + bn] = cb;
        }
    };

    sts(0, ra, rb);
    __syncthreads();
    const int ns = K / 16;
    for (int s = 0; s < ns; s++) {
        if (s + 1 < ns) {
            int k0 = (s + 1) * 16;
            ra = la4(am, k0 + ak);
            rb = BT ? lb4(btn, k0 + btk) : lb4(k0 + bk, bn);
        }
        const uint32_t* A = sA + (s & 1) * ABUF;
        const uint32_t* B = sB + (s & 1) * BBUF;
        #pragma unroll
        for (int kk = 0; kk < 16; kk += 8) {
            uint32_t af[2][4], bf[2][2];
            #pragma unroll
            for (int mi = 0; mi < 2; mi++) {
                int mb = wm0 + mi * 16;
                af[mi][0] = A[(mb + g) * SAS + kk + t];
                af[mi][1] = A[(mb + 8 + g) * SAS + kk + t];
                af[mi][2] = A[(mb + g) * SAS + kk + t + 4];
                af[mi][3] = A[(mb + 8 + g) * SAS + kk + t + 4];
            }
            #pragma unroll
            for (int ni = 0; ni < 2; ni++) {
                int nb_ = wn0 + ni * 8 + g;
                bf[ni][0] = B[(kk + t) * SBS + nb_];
                bf[ni][1] = B[(kk + t + 4) * SBS + nb_];
            }
            #pragma unroll
            for (int mi = 0; mi < 2; mi++)
                #pragma unroll
                for (int ni = 0; ni < 2; ni++)
                    mma8(acc[mi][ni], af[mi], bf[ni]);
        }
        if (s + 1 < ns) { sts((s + 1) & 1, ra, rb); __syncthreads(); }
    }
    __syncthreads();   // protect smem reuse by next tile

    #pragma unroll
    for (int mi = 0; mi < 2; mi++)
        #pragma unroll
        for (int ni = 0; ni < 2; ni++) {
            int r = wm0 + mi * 16 + g, c = wn0 + ni * 8 + 2 * t;
            ep(r,     c,     acc[mi][ni][0]);
            ep(r,     c + 1, acc[mi][ni][1]);
            ep(r + 8, c,     acc[mi][ni][2]);
            ep(r + 8, c + 1, acc[mi][ni][3]);
        }
}

__device__ __forceinline__ float4 ld4(const float* p) { return *(const float4*)p; }

// ---------------- warp LayerNorm over a 768-row ----------------
__device__ __forceinline__ void ln_row(const float* __restrict__ x,
                                       const float* __restrict__ g,
                                       const float* __restrict__ b,
                                       float* __restrict__ o) {
    int lane = threadIdx.x & 31;
    float v[24];
    float s = 0.f, q = 0.f;
    #pragma unroll
    for (int i = 0; i < 24; i++) {
        v[i] = x[lane + 32 * i];
        s += v[i];
        q += v[i] * v[i];
    }
    #pragma unroll
    for (int off = 16; off; off >>= 1) {
        s += __shfl_xor_sync(0xffffffffu, s, off);
        q += __shfl_xor_sync(0xffffffffu, q, off);
    }
    float mu  = s * (1.f / 768.f);
    float inv = rsqrtf(q * (1.f / 768.f) - mu * mu + 1e-5f);
    #pragma unroll
    for (int i = 0; i < 24; i++) {
        int idx = lane + 32 * i;
        o[idx] = (v[i] - mu) * inv * g[idx] + b[idx];
    }
}

// ---------------- The single persistent kernel ----------------
__global__ void __launch_bounds__(TPB, 2) fused_kernel(Params P) {
    __shared__ uint32_t sA[2 * ABUF];
    __shared__ uint32_t sB[2 * BBUF];
    const int nb = P.nb;
    const int bid = blockIdx.x;
    const int wglob = bid * 8 + (threadIdx.x >> 5);
    const int nwarp = nb * 8;
    const int lane32 = threadIdx.x & 31;

    // ---- Stage 1: LayerNorms + 4 modulation GEMMs ----
    for (int r = wglob; r < 1280; r += nwarp) {
        if (r < 256) ln_row(P.recv + r * 768, P.lnrg, P.lnrb, g_r + r * 768);
        else {
            int rr = r - 256;
            ln_row(P.send + rr * 768, P.lnsg, P.lnsb, g_s + rr * 768);
        }
    }
    for (int tt = bid; tt < 176; tt += nb) {
        const float* W; float* O; int N; int lt;
        if (tt < 144) {
            int sel = tt / 48; lt = tt % 48; N = 768;
            W = sel == 0 ? P.Wmq : (sel == 1 ? P.Wmk : P.Wmv);
            O = sel == 0 ? g_mq : (sel == 1 ? g_mk : g_mv);
        } else { lt = tt - 144; W = P.Wme; O = g_me; N = 512; }
        int m0 = (lt & 3) * 64, n0 = (lt >> 2) * 64;
        gemm_block<false>(384, sA, sB,
            [&](int m, int k) { return ld4(&P.codes[(m0 + m) * 384 + k]); },
            [&](int k, int n) { return ld4(&W[k * N + n0 + n]); },
            [&](int m, int n, float a) { O[(m0 + m) * N + n0 + n] = a; });
    }
    grid_bar(nb);

    // ---- Stage 2: q = (r*(1+mq)) @ Wq + bq   [256,768]x[768,512] ----
    for (int tt = bid; tt < 32; tt += nb) {
        int m0 = (tt & 3) * 64, n0 = (tt >> 2) * 64;
        gemm_block<false>(768, sA, sB,
            [&](int m, int k) {
                long i = (long)(m0 + m) * 768 + k;
                float4 r = ld4(&g_r[i]), q = ld4(&g_mq[i]);
                float4 o; o.x = r.x * (1.f + q.x); o.y = r.y * (1.f + q.y);
                o.z = r.z * (1.f + q.z); o.w = r.w * (1.f + q.w);
                return o;
            },
            [&](int k, int n) { return ld4(&P.Wq[k * 512 + n0 + n]); },
            [&](int m, int n, float a) { g_q[(m0 + m) * 512 + n0 + n] = a + P.bq[n0 + n]; });
    }
    grid_bar(nb);

    // ---- Stage 3: qbk dots + Ak = (Wk_h^T q_h)*(1+mk)  per-head NT, K=64 ----
    for (int w = wglob; w < 2048; w += nwarp) {
        int bu = w >> 3, h = w & 7;
        const float* qp = g_q + bu * 512 + h * 64;
        const float* bp = P.bk + h * 64;
        float s = qp[lane32] * bp[lane32] + qp[lane32 + 32] * bp[lane32 + 32];
        #pragma unroll
        for (int off = 16; off; off >>= 1) s += __shfl_xor_sync(0xffffffffu, s, off);
        if (lane32 == 0) g_qbk[bu * 8 + h] = s;
    }
    for (int tt = bid; tt < 384; tt += nb) {
        int h = tt / 48, lt = tt % 48;
        int m0 = (lt & 3) * 64, n0 = (lt >> 2) * 64;
        gemm_block<true>(64, sA, sB,
            [&](int m, int k) { return ld4(&g_q[(m0 + m) * 512 + h * 64 + k]); },
            [&](int n, int k) { return ld4(&P.Wk[(n0 + n) * 512 + h * 64 + k]); },
            [&](int m, int n, float a) {
                int mg = m0 + m; int b = mg >> 6, u = mg & 63;
                g_Ak[b * 393216 + (h * 64 + u) * 768 + n0 + n] =
                    a * (1.f + g_mk[mg * 768 + n0 + n]);
            });
    }
    grid_bar(nb);

    // ---- Stage 4: scores = (Ak @ s^T + qbk)/8   per-batch NT, K=768 ----
    for (int tt = bid; tt < 128; tt += nb) {
        int b = tt >> 5, lt = tt & 31;
        int m0 = (lt & 7) * 64, n0 = (lt >> 3) * 64;
        gemm_block<true>(768, sA, sB,
            [&](int m, int k) { return ld4(&g_Ak[b * 393216 + (m0 + m) * 768 + k]); },
            [&](int n, int k) { return ld4(&g_s[(b * 256 + n0 + n) * 768 + k]); },
            [&](int m, int n, float a) {
                int mg = m0 + m; int h = mg >> 6, u = mg & 63;
                g_w[b * 131072 + mg * 256 + n0 + n] =
                    (a + g_qbk[(b * 64 + u) * 8 + h]) * 0.125f;
            });
    }
    grid_bar(nb);

    // ---- Stage 5: softmax over v (2048 rows of 256) ----
    for (int r = wglob; r < 2048; r += nwarp) {
        float* p = g_w + r * 256;
        float v[8], mx = -1e30f;
        #pragma unroll
        for (int i = 0; i < 8; i++) { v[i] = p[lane32 + 32 * i]; mx = fmaxf(mx, v[i]); }
        #pragma unroll
        for (int off = 16; off; off >>= 1) mx = fmaxf(mx, __shfl_xor_sync(0xffffffffu, mx, off));
        float sm = 0.f;
        #pragma unroll
        for (int i = 0; i < 8; i++) { v[i] = expf(v[i] - mx); sm += v[i]; }
        #pragma unroll
        for (int off = 16; off; off >>= 1) sm += __shfl_xor_sync(0xffffffffu, sm, off);
        float inv = 1.f / sm;
        #pragma unroll
        for (int i = 0; i < 8; i++) p[lane32 + 32 * i] = v[i] * inv;
    }
    grid_bar(nb);

    // ---- Stage 6: Tm = (w @ s)*(1+mv), per-head remap   per-batch NN, K=256 ----
    for (int tt = bid; tt < 384; tt += nb) {
        int b = tt / 96, lt = tt % 96;
        int m0 = (lt & 7) * 64, n0 = (lt >> 3) * 64;
        gemm_block<false>(256, sA, sB,
            [&](int m, int k) { return ld4(&g_w[b * 131072 + (m0 + m) * 256 + k]); },
            [&](int k, int n) { return ld4(&g_s[(b * 256 + k) * 768 + n0 + n]); },
            [&](int m, int n, float a) {
                int mg = m0 + m; int h = mg >> 6, u = mg & 63; int bu = b * 64 + u;
                g_Tm[(h * 256 + bu) * 768 + n0 + n] = a * (1.f + g_mv[bu * 768 + n0 + n]);
            });
    }
    grid_bar(nb);

    // ---- Stage 7: msg = (Tm_h @ Wv_h + bv)*(1+me)   per-head NN, K=768, N=64 ----
    for (int tt = bid; tt < 32; tt += nb) {
        int h = tt >> 2, lt = tt & 3;
        int m0 = lt * 64;
        gemm_block<false>(768, sA, sB,
            [&](int m, int k) { return ld4(&g_Tm[(h * 256 + m0 + m) * 768 + k]); },
            [&](int k, int n) { return ld4(&P.Wv[k * 512 + h * 64 + n]); },
            [&](int m, int n, float a) {
                int c = h * 64 + n; int mg = m0 + m;
                g_msg[mg * 512 + c] = (a + P.bv[c]) * (1.f + g_me[mg * 512 + c]);
            });
    }
    grid_bar(nb);

    // ---- Stage 8: out = recv + (msg @ We + be)*gamma   [256,512]x[512,768] ----
    for (int tt = bid; tt < 48; tt += nb) {
        int m0 = (tt & 3) * 64, n0 = (tt >> 2) * 64;
        gemm_block<false>(512, sA, sB,
            [&](int m, int k) { return ld4(&g_msg[(m0 + m) * 512 + k]); },
            [&](int k, int n) { return ld4(&P.We[k * 768 + n0 + n]); },
            [&](int m, int n, float a) {
                int mg = m0 + m, c = n0 + n;
                P.out[mg * 768 + c] = P.recv[mg * 768 + c] + (a + P.be[c]) * P.gamma[c];
            });
    }
}

// ---------------- Host launcher ----------------
extern "C" void kernel_launch(void* const* d_in, const int* in_sizes, int n_in,
                              void* d_out, int out_size) {
    (void)in_sizes; (void)n_in; (void)out_size;
    Params P;
    P.recv  = (const float*)d_in[0];
    P.codes = (const float*)d_in[1];
    P.send  = (const float*)d_in[2];
    P.lnrg  = (const float*)d_in[3];
    P.lnrb  = (const float*)d_in[4];
    P.lnsg  = (const float*)d_in[5];
    P.lnsb  = (const float*)d_in[6];
    P.Wq  = (const float*)d_in[7];
    P.bq  = (const float*)d_in[8];
    P.Wmq = (const float*)d_in[9];
    P.Wk  = (const float*)d_in[10];
    P.bk  = (const float*)d_in[11];
    P.Wmk = (const float*)d_in[12];
    P.Wv  = (const float*)d_in[13];
    P.bv  = (const float*)d_in[14];
    P.Wmv = (const float*)d_in[15];
    P.We  = (const float*)d_in[16];
    P.be  = (const float*)d_in[17];
    P.Wme = (const float*)d_in[18];
    P.gamma = (const float*)d_in[19];
    P.out = (float*)d_out;

    int occ = 0;
    cudaOccupancyMaxActiveBlocksPerMultiprocessor(&occ, fused_kernel, TPB, 0);
    if (occ < 1) occ = 1;
    int dev = 0;
    cudaGetDevice(&dev);
    int sms = 0;
    cudaDeviceGetAttribute(&sms, cudaDevAttrMultiProcessorCount, dev);
    if (sms < 1) sms = 1;
    int nb = occ * sms;
    if (nb > 1024) nb = 1024;
    P.nb = nb;

    fused_kernel<<<nb, TPB>>>(P);
}

// round 5
// speedup vs baseline: 2.3862x; 1.2894x over previous
#include <cuda_runtime.h>
#include <cstdint>

#define TPB 256

// B=4, U=64, V=256, DIM=768, CODE=384, INNER=512, HEADS=8, HD=64

struct Params {
    const float *recv, *codes, *send;
    const float *lnrg, *lnrb, *lnsg, *lnsb;
    const float *Wq, *bq, *Wmq, *Wk, *bk, *Wmk;
    const float *Wv, *bv, *Wmv, *We, *be, *Wme, *gamma;
    float* out;
    int nb;
};

// ---------------- Scratch (device globals; no allocs) ----------------
__device__ __align__(16) float g_r  [256 * 768];
__device__ __align__(16) float g_s  [1024 * 768];
__device__ __align__(16) float g_mq [256 * 768];
__device__ __align__(16) float g_mk [256 * 768];
__device__ __align__(16) float g_mv [256 * 768];
__device__ __align__(16) float g_me [256 * 512];
__device__ __align__(16) float g_q  [256 * 512];
__device__ __align__(16) float g_qbk[256 * 8];
__device__ __align__(16) float g_Ak [4 * 512 * 768];
__device__ __align__(16) float g_w  [4 * 512 * 256];       // final softmax weights
// K-split partial buffers (combined in consumer loaders; also reused later)
#define QP 131072      // 256*512
#define WP 524288      // 4*512*256
#define TP 1572864     // 8*256*768
#define OP 196608      // 256*768
__device__ __align__(16) float g_qp[4 * QP];   // q partials; reused as msg partials (S7)
__device__ __align__(16) float g_wp[2 * WP];   // score partials; reused as out partials (S8)
__device__ __align__(16) float g_tp[2 * TP];   // T partials

__device__ unsigned g_barcnt = 0;
__device__ unsigned g_bargen = 0;

__device__ __forceinline__ void grid_bar(int nb) {
    __syncthreads();
    if (threadIdx.x == 0) {
        __threadfence();
        unsigned gen = *(volatile unsigned*)&g_bargen;
        unsigned t = atomicAdd(&g_barcnt, 1u);
        if (t == (unsigned)(nb - 1)) {
            atomicExch(&g_barcnt, 0u);
            __threadfence();
            atomicExch(&g_bargen, gen + 1u);
        } else {
            while (*(volatile unsigned*)&g_bargen == gen) { __nanosleep(32); }
        }
        __threadfence();
    }
    __syncthreads();
}

// ---------------- tf32 helpers ----------------
__device__ __forceinline__ uint32_t f2tf(float x) {
    uint32_t u;
    asm("cvt.rna.tf32.f32 %0, %1;" : "=r"(u) : "f"(x));
    return u;
}
__device__ __forceinline__ void mma8(float* c, const uint32_t* a, const uint32_t* b) {
    asm volatile(
        "mma.sync.aligned.m16n8k8.row.col.f32.tf32.tf32.f32 "
        "{%0,%1,%2,%3}, {%4,%5,%6,%7}, {%8,%9}, {%0,%1,%2,%3};"
        : "+f"(c[0]), "+f"(c[1]), "+f"(c[2]), "+f"(c[3])
        : "r"(a[0]), "r"(a[1]), "r"(a[2]), "r"(a[3]), "r"(b[0]), "r"(b[1]));
}

#define SAS 20
#define SBS 72
#define ABUF (64 * SAS)
#define BBUF (16 * SBS)

// ---------------- block-level 64x64 tf32 GEMM, double-buffered smem ------
template<bool BT, class LA, class LB, class EP>
__device__ __forceinline__ void gemm_block(int K, uint32_t* sA, uint32_t* sB,
                                           LA la4, LB lb4, EP ep) {
    const int tid = threadIdx.x;
    const int l = tid & 31, g = l >> 2, t = l & 3;
    const int wid = tid >> 5;
    const int wm0 = (wid & 1) * 32, wn0 = (wid >> 1) * 16;
    const int am = tid >> 2, ak = (tid & 3) * 4;
    const int bk = tid >> 4, bn = (tid & 15) * 4;
    const int btn = tid >> 2, btk = (tid & 3) * 4;

    float acc[2][2][4];
    #pragma unroll
    for (int i = 0; i < 2; i++)
        #pragma unroll
        for (int j = 0; j < 2; j++)
            #pragma unroll
            for (int e = 0; e < 4; e++) acc[i][j][e] = 0.f;

    float4 ra = la4(am, ak);
    float4 rb = BT ? lb4(btn, btk) : lb4(bk, bn);

    auto sts = [&](int p, const float4& va, const float4& vb) {
        uint32_t* A = sA + p * ABUF;
        uint32_t* B = sB + p * BBUF;
        uint4 ca; ca.x = f2tf(va.x); ca.y = f2tf(va.y); ca.z = f2tf(va.z); ca.w = f2tf(va.w);
        *(uint4*)&A[am * SAS + ak] = ca;
        if (BT) {
            B[(btk + 0) * SBS + btn] = f2tf(vb.x);
            B[(btk + 1) * SBS + btn] = f2tf(vb.y);
            B[(btk + 2) * SBS + btn] = f2tf(vb.z);
            B[(btk + 3) * SBS + btn] = f2tf(vb.w);
        } else {
            uint4 cb; cb.x = f2tf(vb.x); cb.y = f2tf(vb.y); cb.z = f2tf(vb.z); cb.w = f2tf(vb.w);
            *(uint4*)&B[bk * SBS + bn] = cb;
        }
    };

    sts(0, ra, rb);
    __syncthreads();
    const int ns = K / 16;
    for (int s = 0; s < ns; s++) {
        if (s + 1 < ns) {
            int k0 = (s + 1) * 16;
            ra = la4(am, k0 + ak);
            rb = BT ? lb4(btn, k0 + btk) : lb4(k0 + bk, bn);
        }
        const uint32_t* A = sA + (s & 1) * ABUF;
        const uint32_t* B = sB + (s & 1) * BBUF;
        #pragma unroll
        for (int kk = 0; kk < 16; kk += 8) {
            uint32_t af[2][4], bf[2][2];
            #pragma unroll
            for (int mi = 0; mi < 2; mi++) {
                int mb = wm0 + mi * 16;
                af[mi][0] = A[(mb + g) * SAS + kk + t];
                af[mi][1] = A[(mb + 8 + g) * SAS + kk + t];
                af[mi][2] = A[(mb + g) * SAS + kk + t + 4];
                af[mi][3] = A[(mb + 8 + g) * SAS + kk + t + 4];
            }
            #pragma unroll
            for (int ni = 0; ni < 2; ni++) {
                int nb_ = wn0 + ni * 8 + g;
                bf[ni][0] = B[(kk + t) * SBS + nb_];
                bf[ni][1] = B[(kk + t + 4) * SBS + nb_];
            }
            #pragma unroll
            for (int mi = 0; mi < 2; mi++)
                #pragma unroll
                for (int ni = 0; ni < 2; ni++)
                    mma8(acc[mi][ni], af[mi], bf[ni]);
        }
        if (s + 1 < ns) { sts((s + 1) & 1, ra, rb); __syncthreads(); }
    }
    __syncthreads();

    #pragma unroll
    for (int mi = 0; mi < 2; mi++)
        #pragma unroll
        for (int ni = 0; ni < 2; ni++) {
            int r = wm0 + mi * 16 + g, c = wn0 + ni * 8 + 2 * t;
            ep(r,     c,     acc[mi][ni][0]);
            ep(r,     c + 1, acc[mi][ni][1]);
            ep(r + 8, c,     acc[mi][ni][2]);
            ep(r + 8, c + 1, acc[mi][ni][3]);
        }
}

__device__ __forceinline__ float4 ld4(const float* p) { return *(const float4*)p; }

// ---------------- warp LayerNorm over a 768-row ----------------
__device__ __forceinline__ void ln_row(const float* __restrict__ x,
                                       const float* __restrict__ g,
                                       const float* __restrict__ b,
                                       float* __restrict__ o) {
    int lane = threadIdx.x & 31;
    float v[24];
    float s = 0.f, q = 0.f;
    #pragma unroll
    for (int i = 0; i < 24; i++) {
        v[i] = x[lane + 32 * i];
        s += v[i];
        q += v[i] * v[i];
    }
    #pragma unroll
    for (int off = 16; off; off >>= 1) {
        s += __shfl_xor_sync(0xffffffffu, s, off);
        q += __shfl_xor_sync(0xffffffffu, q, off);
    }
    float mu  = s * (1.f / 768.f);
    float inv = rsqrtf(q * (1.f / 768.f) - mu * mu + 1e-5f);
    #pragma unroll
    for (int i = 0; i < 24; i++) {
        int idx = lane + 32 * i;
        o[idx] = (v[i] - mu) * inv * g[idx] + b[idx];
    }
}

// ---------------- The single persistent kernel ----------------
__global__ void __launch_bounds__(TPB, 3) fused_kernel(Params P) {
    __shared__ uint32_t sA[2 * ABUF];
    __shared__ uint32_t sB[2 * BBUF];
    const int nb = P.nb;
    const int bid = blockIdx.x;
    const int wglob = bid * 8 + (threadIdx.x >> 5);
    const int nwarp = nb * 8;
    const int lane32 = threadIdx.x & 31;

    // ---- S1: LayerNorms + 4 modulation GEMMs ----
    for (int r = wglob; r < 1280; r += nwarp) {
        if (r < 256) ln_row(P.recv + r * 768, P.lnrg, P.lnrb, g_r + r * 768);
        else {
            int rr = r - 256;
            ln_row(P.send + rr * 768, P.lnsg, P.lnsb, g_s + rr * 768);
        }
    }
    for (int tt = bid; tt < 176; tt += nb) {
        const float* W; float* O; int N; int lt;
        if (tt < 144) {
            int sel = tt / 48; lt = tt % 48; N = 768;
            W = sel == 0 ? P.Wmq : (sel == 1 ? P.Wmk : P.Wmv);
            O = sel == 0 ? g_mq : (sel == 1 ? g_mk : g_mv);
        } else { lt = tt - 144; W = P.Wme; O = g_me; N = 512; }
        int m0 = (lt & 3) * 64, n0 = (lt >> 2) * 64;
        gemm_block<false>(384, sA, sB,
            [&](int m, int k) { return ld4(&P.codes[(m0 + m) * 384 + k]); },
            [&](int k, int n) { return ld4(&W[k * N + n0 + n]); },
            [&](int m, int n, float a) { O[(m0 + m) * N + n0 + n] = a; });
    }
    grid_bar(nb);

    // ---- S2: q partials, K split x4 (K=192 each): 128 tiles ----
    for (int tt = bid; tt < 128; tt += nb) {
        int kp = tt >> 5, lt = tt & 31;
        int m0 = (lt & 3) * 64, n0 = (lt >> 2) * 64, kb = kp * 192;
        gemm_block<false>(192, sA, sB,
            [&](int m, int k) {
                long i = (long)(m0 + m) * 768 + kb + k;
                float4 r = ld4(&g_r[i]), q = ld4(&g_mq[i]);
                float4 o; o.x = r.x * (1.f + q.x); o.y = r.y * (1.f + q.y);
                o.z = r.z * (1.f + q.z); o.w = r.w * (1.f + q.w);
                return o;
            },
            [&](int k, int n) { return ld4(&P.Wq[(kb + k) * 512 + n0 + n]); },
            [&](int m, int n, float a) { g_qp[kp * QP + (m0 + m) * 512 + n0 + n] = a; });
    }
    grid_bar(nb);

    // ---- S2b: q = sum(partials)+bq ; qbk = q_h . bk_h  (warp per (bu,h)) ----
    for (int w = wglob; w < 2048; w += nwarp) {
        int bu = w >> 3, h = w & 7;
        int base = bu * 512 + h * 64;
        int c0 = h * 64 + lane32, c1 = c0 + 32;
        float q0 = g_qp[base + lane32] + g_qp[QP + base + lane32] +
                   g_qp[2 * QP + base + lane32] + g_qp[3 * QP + base + lane32] + P.bq[c0];
        float q1 = g_qp[base + lane32 + 32] + g_qp[QP + base + lane32 + 32] +
                   g_qp[2 * QP + base + lane32 + 32] + g_qp[3 * QP + base + lane32 + 32] + P.bq[c1];
        g_q[base + lane32] = q0;
        g_q[base + lane32 + 32] = q1;
        float s = q0 * P.bk[c0] + q1 * P.bk[c1];
        #pragma unroll
        for (int off = 16; off; off >>= 1) s += __shfl_xor_sync(0xffffffffu, s, off);
        if (lane32 == 0) g_qbk[bu * 8 + h] = s;
    }
    grid_bar(nb);

    // ---- S3: Ak = (Wk_h^T q_h)*(1+mk)  per-head NT, K=64: 384 tiles ----
    for (int tt = bid; tt < 384; tt += nb) {
        int h = tt / 48, lt = tt % 48;
        int m0 = (lt & 3) * 64, n0 = (lt >> 2) * 64;
        gemm_block<true>(64, sA, sB,
            [&](int m, int k) { return ld4(&g_q[(m0 + m) * 512 + h * 64 + k]); },
            [&](int n, int k) { return ld4(&P.Wk[(n0 + n) * 512 + h * 64 + k]); },
            [&](int m, int n, float a) {
                int mg = m0 + m; int b = mg >> 6, u = mg & 63;
                g_Ak[b * 393216 + (h * 64 + u) * 768 + n0 + n] =
                    a * (1.f + g_mk[mg * 768 + n0 + n]);
            });
    }
    grid_bar(nb);

    // ---- S4: score partials, K split x2 (K=384): 256 tiles ----
    for (int tt = bid; tt < 256; tt += nb) {
        int kp = tt >> 7, lt = tt & 127;
        int b = lt >> 5, l2 = lt & 31;
        int m0 = (l2 & 7) * 64, n0 = (l2 >> 3) * 64, kb = kp * 384;
        gemm_block<true>(384, sA, sB,
            [&](int m, int k) { return ld4(&g_Ak[b * 393216 + (m0 + m) * 768 + kb + k]); },
            [&](int n, int k) { return ld4(&g_s[(b * 256 + n0 + n) * 768 + kb + k]); },
            [&](int m, int n, float a) {
                g_wp[kp * WP + b * 131072 + (m0 + m) * 256 + n0 + n] = a;
            });
    }
    grid_bar(nb);

    // ---- S5: softmax( (wp0+wp1+qbk)/8 ) -> g_w ----
    for (int r = wglob; r < 2048; r += nwarp) {
        int b = r >> 9, mg = r & 511;
        int h = mg >> 6, u = mg & 63;
        float qb = g_qbk[(b * 64 + u) * 8 + h];
        long base = (long)b * 131072 + (long)mg * 256;
        float v[8], mx = -1e30f;
        #pragma unroll
        for (int i = 0; i < 8; i++) {
            long idx = base + lane32 + 32 * i;
            v[i] = (g_wp[idx] + g_wp[WP + idx] + qb) * 0.125f;
            mx = fmaxf(mx, v[i]);
        }
        #pragma unroll
        for (int off = 16; off; off >>= 1) mx = fmaxf(mx, __shfl_xor_sync(0xffffffffu, mx, off));
        float sm = 0.f;
        #pragma unroll
        for (int i = 0; i < 8; i++) { v[i] = expf(v[i] - mx); sm += v[i]; }
        #pragma unroll
        for (int off = 16; off; off >>= 1) sm += __shfl_xor_sync(0xffffffffu, sm, off);
        float inv = 1.f / sm;
        #pragma unroll
        for (int i = 0; i < 8; i++) g_w[base + lane32 + 32 * i] = v[i] * inv;
    }
    grid_bar(nb);

    // ---- S6: T partials = w @ s, K split x2 (K=128): 768 tiles ----
    for (int tt = bid; tt < 768; tt += nb) {
        int kp = tt / 384, lt = tt % 384;
        int b = lt / 96, l2 = lt % 96;
        int m0 = (l2 & 7) * 64, n0 = (l2 >> 3) * 64, kb = kp * 128;
        gemm_block<false>(128, sA, sB,
            [&](int m, int k) { return ld4(&g_w[b * 131072 + (m0 + m) * 256 + kb + k]); },
            [&](int k, int n) { return ld4(&g_s[(b * 256 + kb + k) * 768 + n0 + n]); },
            [&](int m, int n, float a) {
                g_tp[kp * TP + b * 393216 + (m0 + m) * 768 + n0 + n] = a;
            });
    }
    grid_bar(nb);

    // ---- S7: msg partials = ((tp0+tp1)*(1+mv))_h @ Wv_h, K split x4: 128 tiles ----
    for (int tt = bid; tt < 128; tt += nb) {
        int kp = tt >> 5, lt = tt & 31;
        int h = lt >> 2, m0 = (lt & 3) * 64, kb = kp * 192;
        gemm_block<false>(192, sA, sB,
            [&](int m, int k) {
                int bu = m0 + m; int b = bu >> 6, u = bu & 63;
                long ti = (long)b * 393216 + (long)(h * 64 + u) * 768 + kb + k;
                float4 t0 = ld4(&g_tp[ti]), t1 = ld4(&g_tp[TP + ti]);
                float4 mv = ld4(&g_mv[(long)bu * 768 + kb + k]);
                float4 o;
                o.x = (t0.x + t1.x) * (1.f + mv.x);
                o.y = (t0.y + t1.y) * (1.f + mv.y);
                o.z = (t0.z + t1.z) * (1.f + mv.z);
                o.w = (t0.w + t1.w) * (1.f + mv.w);
                return o;
            },
            [&](int k, int n) { return ld4(&P.Wv[(kb + k) * 512 + h * 64 + n]); },
            [&](int m, int n, float a) {
                g_qp[kp * QP + (m0 + m) * 512 + h * 64 + n] = a;   // reuse qp
            });
    }
    grid_bar(nb);

    // ---- S8: out partials = msg_mod @ We, K split x2 (K=256): 96 tiles ----
    for (int tt = bid; tt < 96; tt += nb) {
        int kp = tt / 48, lt = tt % 48;
        int m0 = (lt & 3) * 64, n0 = (lt >> 2) * 64, kb = kp * 256;
        gemm_block<false>(256, sA, sB,
            [&](int m, int k) {
                int mg = m0 + m; long i = (long)mg * 512 + kb + k;
                float4 p0 = ld4(&g_qp[i]), p1 = ld4(&g_qp[QP + i]);
                float4 p2 = ld4(&g_qp[2 * QP + i]), p3 = ld4(&g_qp[3 * QP + i]);
                float4 bv = ld4(&P.bv[kb + k]), me = ld4(&g_me[i]);
                float4 o;
                o.x = (p0.x + p1.x + p2.x + p3.x + bv.x) * (1.f + me.x);
                o.y = (p0.y + p1.y + p2.y + p3.y + bv.y) * (1.f + me.y);
                o.z = (p0.z + p1.z + p2.z + p3.z + bv.z) * (1.f + me.z);
                o.w = (p0.w + p1.w + p2.w + p3.w + bv.w) * (1.f + me.w);
                return o;
            },
            [&](int k, int n) { return ld4(&P.We[(kb + k) * 768 + n0 + n]); },
            [&](int m, int n, float a) {
                g_wp[kp * OP + (m0 + m) * 768 + n0 + n] = a;       // reuse wp
            });
    }
    grid_bar(nb);

    // ---- S9: out = recv + (op0+op1+be)*gamma (vectorized elementwise) ----
    {
        int nth = nwarp * 32;
        int gt = wglob * 32 + lane32;
        for (int i = gt; i < 49152; i += nth) {   // 196608/4 float4s
            long idx = (long)i * 4;
            int c = (int)(idx % 768);
            float4 p0 = ld4(&g_wp[idx]), p1 = ld4(&g_wp[OP + idx]);
            float4 be = ld4(&P.be[c]), ga = ld4(&P.gamma[c]);
            float4 rv = ld4(&P.recv[idx]);
            float4 o;
            o.x = rv.x + (p0.x + p1.x + be.x) * ga.x;
            o.y = rv.y + (p0.y + p1.y + be.y) * ga.y;
            o.z = rv.z + (p0.z + p1.z + be.z) * ga.z;
            o.w = rv.w + (p0.w + p1.w + be.w) * ga.w;
            *(float4*)&P.out[idx] = o;
        }
    }
}

// ---------------- Host launcher ----------------
extern "C" void kernel_launch(void* const* d_in, const int* in_sizes, int n_in,
                              void* d_out, int out_size) {
    (void)in_sizes; (void)n_in; (void)out_size;
    Params P;
    P.recv  = (const float*)d_in[0];
    P.codes = (const float*)d_in[1];
    P.send  = (const float*)d_in[2];
    P.lnrg  = (const float*)d_in[3];
    P.lnrb  = (const float*)d_in[4];
    P.lnsg  = (const float*)d_in[5];
    P.lnsb  = (const float*)d_in[6];
    P.Wq  = (const float*)d_in[7];
    P.bq  = (const float*)d_in[8];
    P.Wmq = (const float*)d_in[9];
    P.Wk  = (const float*)d_in[10];
    P.bk  = (const float*)d_in[11];
    P.Wmk = (const float*)d_in[12];
    P.Wv  = (const float*)d_in[13];
    P.bv  = (const float*)d_in[14];
    P.Wmv = (const float*)d_in[15];
    P.We  = (const float*)d_in[16];
    P.be  = (const float*)d_in[17];
    P.Wme = (const float*)d_in[18];
    P.gamma = (const float*)d_in[19];
    P.out = (float*)d_out;

    int occ = 0;
    cudaOccupancyMaxActiveBlocksPerMultiprocessor(&occ, fused_kernel, TPB, 0);
    if (occ < 1) occ = 1;
    int dev = 0;
    cudaGetDevice(&dev);
    int sms = 0;
    cudaDeviceGetAttribute(&sms, cudaDevAttrMultiProcessorCount, dev);
    if (sms < 1) sms = 1;
    int nb = occ * sms;
    if (nb > 1024) nb = 1024;
    P.nb = nb;

    fused_kernel<<<nb, TPB>>>(P);
}

// round 8
// speedup vs baseline: 2.7579x; 1.1558x over previous
#include <cuda_runtime.h>
#include <cstdint>

#define TPB 256

// B=4, U=64, V=256, DIM=768, CODE=384, INNER=512, HEADS=8, HD=64

struct Params {
    const float *recv, *codes, *send;
    const float *lnrg, *lnrb, *lnsg, *lnsb;
    const float *Wq, *bq, *Wmq, *Wk, *bk, *Wmk;
    const float *Wv, *bv, *Wmv, *We, *be, *Wme, *gamma;
    float* out;
    int nb;
};

// ---------------- Scratch (device globals; no allocs) ----------------
__device__ __align__(16) float g_r  [256 * 768];
__device__ __align__(16) float g_s  [1024 * 768];
__device__ __align__(16) float g_rq [256 * 768];   // r*(1+mq), via S1 epilogue
__device__ __align__(16) float g_mk [256 * 768];
__device__ __align__(16) float g_mv [256 * 768];
__device__ __align__(16) float g_me [256 * 512];
__device__ __align__(16) float g_q  [256 * 512];
__device__ __align__(16) float g_qbk[256 * 8];
__device__ __align__(16) float g_Ak [4 * 512 * 768];
__device__ __align__(16) float g_w  [4 * 512 * 256];
__device__ __align__(16) float g_Tm [8 * 256 * 768];
__device__ __align__(16) float g_msg[256 * 512];
#define QP 131072      // 256*512
#define WP 524288      // 4*512*256
#define OP 196608      // 256*768
__device__ __align__(16) float g_qp[8 * QP];   // q partials; reused as msg partials
__device__ __align__(16) float g_wp[3 * WP];   // score partials (3); reused as 8 out partials

__device__ unsigned g_barcnt = 0;
__device__ unsigned g_bargen = 0;

__device__ __forceinline__ void grid_bar(int nb) {
    __syncthreads();
    if (threadIdx.x == 0) {
        __threadfence();
        unsigned gen = *(volatile unsigned*)&g_bargen;
        unsigned t = atomicAdd(&g_barcnt, 1u);
        if (t == (unsigned)(nb - 1)) {
            atomicExch(&g_barcnt, 0u);
            __threadfence();
            atomicExch(&g_bargen, gen + 1u);
        } else {
            while (*(volatile unsigned*)&g_bargen == gen) { __nanosleep(32); }
        }
        __threadfence();
    }
    __syncthreads();
}

// ---------------- tf32 helpers ----------------
__device__ __forceinline__ uint32_t f2tf(float x) {
    uint32_t u;
    asm("cvt.rna.tf32.f32 %0, %1;" : "=r"(u) : "f"(x));
    return u;
}
__device__ __forceinline__ void mma8(float* c, const uint32_t* a, const uint32_t* b) {
    asm volatile(
        "mma.sync.aligned.m16n8k8.row.col.f32.tf32.tf32.f32 "
        "{%0,%1,%2,%3}, {%4,%5,%6,%7}, {%8,%9}, {%0,%1,%2,%3};"
        : "+f"(c[0]), "+f"(c[1]), "+f"(c[2]), "+f"(c[3])
        : "r"(a[0]), "r"(a[1]), "r"(a[2]), "r"(a[3]), "r"(b[0]), "r"(b[1]));
}

#define SAS 20
#define SBS 72
#define ABUF (64 * SAS)    // 1280
#define BBUF (16 * SBS)    // 1152

// ---- R5-verified synchronous 64x64 tf32 GEMM, double-buffered smem ----
// C(m,n)=sum_k A(m,k)*B(k,n); K%16==0.
// la4(m,k)->float4 A(m,k..k+3). BT=false: lb4(k,n)->float4 B(k,n..n+3);
// BT=true: lb4(n,k)->float4 B(n, k..k+3) (transposed at STS).
template<bool BT, class LA, class LB, class EP>
__device__ __forceinline__ void gemm_block(int K, uint32_t* sA, uint32_t* sB,
                                           LA la4, LB lb4, EP ep) {
    const int tid = threadIdx.x;
    const int l = tid & 31, g = l >> 2, t = l & 3;
    const int wid = tid >> 5;
    const int wm0 = (wid & 1) * 32, wn0 = (wid >> 1) * 16;
    const int am = tid >> 2, ak = (tid & 3) * 4;
    const int bk = tid >> 4, bn = (tid & 15) * 4;
    const int btn = tid >> 2, btk = (tid & 3) * 4;

    float acc[2][2][4];
    #pragma unroll
    for (int i = 0; i < 2; i++)
        #pragma unroll
        for (int j = 0; j < 2; j++)
            #pragma unroll
            for (int e = 0; e < 4; e++) acc[i][j][e] = 0.f;

    float4 ra = la4(am, ak);
    float4 rb = BT ? lb4(btn, btk) : lb4(bk, bn);

    auto sts = [&](int p, const float4& va, const float4& vb) {
        uint32_t* A = sA + p * ABUF;
        uint32_t* B = sB + p * BBUF;
        uint4 ca; ca.x = f2tf(va.x); ca.y = f2tf(va.y); ca.z = f2tf(va.z); ca.w = f2tf(va.w);
        *(uint4*)&A[am * SAS + ak] = ca;
        if (BT) {
            B[(btk + 0) * SBS + btn] = f2tf(vb.x);
            B[(btk + 1) * SBS + btn] = f2tf(vb.y);
            B[(btk + 2) * SBS + btn] = f2tf(vb.z);
            B[(btk + 3) * SBS + btn] = f2tf(vb.w);
        } else {
            uint4 cb; cb.x = f2tf(vb.x); cb.y = f2tf(vb.y); cb.z = f2tf(vb.z); cb.w = f2tf(vb.w);
            *(uint4*)&B[bk * SBS + bn] = cb;
        }
    };

    sts(0, ra, rb);
    __syncthreads();
    const int ns = K / 16;
    for (int s = 0; s < ns; s++) {
        if (s + 1 < ns) {
            int k0 = (s + 1) * 16;
            ra = la4(am, k0 + ak);
            rb = BT ? lb4(btn, k0 + btk) : lb4(k0 + bk, bn);
        }
        const uint32_t* A = sA + (s & 1) * ABUF;
        const uint32_t* B = sB + (s & 1) * BBUF;
        #pragma unroll
        for (int kk = 0; kk < 16; kk += 8) {
            uint32_t af[2][4], bf[2][2];
            #pragma unroll
            for (int mi = 0; mi < 2; mi++) {
                int mb = wm0 + mi * 16;
                af[mi][0] = A[(mb + g) * SAS + kk + t];
                af[mi][1] = A[(mb + 8 + g) * SAS + kk + t];
                af[mi][2] = A[(mb + g) * SAS + kk + t + 4];
                af[mi][3] = A[(mb + 8 + g) * SAS + kk + t + 4];
            }
            #pragma unroll
            for (int ni = 0; ni < 2; ni++) {
                int nb_ = wn0 + ni * 8 + g;
                bf[ni][0] = B[(kk + t) * SBS + nb_];
                bf[ni][1] = B[(kk + t + 4) * SBS + nb_];
            }
            #pragma unroll
            for (int mi = 0; mi < 2; mi++)
                #pragma unroll
                for (int ni = 0; ni < 2; ni++)
                    mma8(acc[mi][ni], af[mi], bf[ni]);
        }
        if (s + 1 < ns) { sts((s + 1) & 1, ra, rb); }
        __syncthreads();
    }

    #pragma unroll
    for (int mi = 0; mi < 2; mi++)
        #pragma unroll
        for (int ni = 0; ni < 2; ni++) {
            int r = wm0 + mi * 16 + g, c = wn0 + ni * 8 + 2 * t;
            ep(r,     c,     acc[mi][ni][0]);
            ep(r,     c + 1, acc[mi][ni][1]);
            ep(r + 8, c,     acc[mi][ni][2]);
            ep(r + 8, c + 1, acc[mi][ni][3]);
        }
}

__device__ __forceinline__ float4 ld4(const float* p) { return *(const float4*)p; }

// ---------------- warp LayerNorm over a 768-row ----------------
__device__ __forceinline__ void ln_row(const float* __restrict__ x,
                                       const float* __restrict__ g,
                                       const float* __restrict__ b,
                                       float* __restrict__ o) {
    int lane = threadIdx.x & 31;
    float v[24];
    float s = 0.f, q = 0.f;
    #pragma unroll
    for (int i = 0; i < 24; i++) {
        v[i] = x[lane + 32 * i];
        s += v[i];
        q += v[i] * v[i];
    }
    #pragma unroll
    for (int off = 16; off; off >>= 1) {
        s += __shfl_xor_sync(0xffffffffu, s, off);
        q += __shfl_xor_sync(0xffffffffu, q, off);
    }
    float mu  = s * (1.f / 768.f);
    float inv = rsqrtf(q * (1.f / 768.f) - mu * mu + 1e-5f);
    #pragma unroll
    for (int i = 0; i < 24; i++) {
        int idx = lane + 32 * i;
        o[idx] = (v[i] - mu) * inv * g[idx] + b[idx];
    }
}

// ---------------- The single persistent kernel ----------------
__global__ void __launch_bounds__(TPB, 3) fused_kernel(Params P) {
    __shared__ __align__(16) uint32_t sA[2 * ABUF];
    __shared__ __align__(16) uint32_t sB[2 * BBUF];
    const int nb = P.nb;
    const int bid = blockIdx.x;
    const int wglob = bid * 8 + (threadIdx.x >> 5);
    const int nwarp = nb * 8;
    const int lane32 = threadIdx.x & 31;

    // ---- S0: LayerNorms ----
    for (int r = wglob; r < 1280; r += nwarp) {
        if (r < 256) ln_row(P.recv + r * 768, P.lnrg, P.lnrb, g_r + r * 768);
        else {
            int rr = r - 256;
            ln_row(P.send + rr * 768, P.lnsg, P.lnsb, g_s + rr * 768);
        }
    }
    grid_bar(nb);

    // ---- S1: 4 modulation GEMMs; mq-tiles write rq = r*(1+mq) ----
    for (int tt = bid; tt < 176; tt += nb) {
        const float* W; float* O; int N; int lt; int mode;
        if (tt < 144) {
            int sel = tt / 48; lt = tt % 48; N = 768;
            W = sel == 0 ? P.Wmq : (sel == 1 ? P.Wmk : P.Wmv);
            O = sel == 0 ? g_rq : (sel == 1 ? g_mk : g_mv);
            mode = (sel == 0) ? 0 : 1;
        } else { lt = tt - 144; W = P.Wme; O = g_me; N = 512; mode = 1; }
        int m0 = (lt & 3) * 64, n0 = (lt >> 2) * 64;
        gemm_block<false>(384, sA, sB,
            [&](int m, int k) { return ld4(&P.codes[(m0 + m) * 384 + k]); },
            [&](int k, int n) { return ld4(&W[k * N + n0 + n]); },
            [&](int m, int n, float a) {
                long o = (long)(m0 + m) * N + n0 + n;
                if (mode == 0) O[o] = g_r[o] * (1.f + a);
                else O[o] = a;
            });
    }
    grid_bar(nb);

    // ---- S2: q partials, K split x8 (K=96): 256 tiles ----
    for (int tt = bid; tt < 256; tt += nb) {
        int kp = tt >> 5, lt = tt & 31;
        int m0 = (lt & 3) * 64, n0 = (lt >> 2) * 64, kb = kp * 96;
        gemm_block<false>(96, sA, sB,
            [&](int m, int k) { return ld4(&g_rq[(m0 + m) * 768 + kb + k]); },
            [&](int k, int n) { return ld4(&P.Wq[(kb + k) * 512 + n0 + n]); },
            [&](int m, int n, float a) { g_qp[kp * QP + (m0 + m) * 512 + n0 + n] = a; });
    }
    grid_bar(nb);

    // ---- S2b: q = sum(8 partials)+bq ; qbk = q_h . bk_h ----
    for (int w = wglob; w < 2048; w += nwarp) {
        int bu = w >> 3, h = w & 7;
        int base = bu * 512 + h * 64;
        int c0 = h * 64 + lane32, c1 = c0 + 32;
        float q0 = P.bq[c0], q1 = P.bq[c1];
        #pragma unroll
        for (int p = 0; p < 8; p++) {
            q0 += g_qp[p * QP + base + lane32];
            q1 += g_qp[p * QP + base + lane32 + 32];
        }
        g_q[base + lane32] = q0;
        g_q[base + lane32 + 32] = q1;
        float s = q0 * P.bk[c0] + q1 * P.bk[c1];
        #pragma unroll
        for (int off = 16; off; off >>= 1) s += __shfl_xor_sync(0xffffffffu, s, off);
        if (lane32 == 0) g_qbk[bu * 8 + h] = s;
    }
    grid_bar(nb);

    // ---- S3: Ak = (Wk_h^T q_h)*(1+mk)  per-head NT, K=64: 384 tiles ----
    for (int tt = bid; tt < 384; tt += nb) {
        int h = tt / 48, lt = tt % 48;
        int m0 = (lt & 3) * 64, n0 = (lt >> 2) * 64;
        gemm_block<true>(64, sA, sB,
            [&](int m, int k) { return ld4(&g_q[(m0 + m) * 512 + h * 64 + k]); },
            [&](int n, int k) { return ld4(&P.Wk[(n0 + n) * 512 + h * 64 + k]); },
            [&](int m, int n, float a) {
                int mg = m0 + m; int b = mg >> 6, u = mg & 63;
                g_Ak[b * 393216 + (h * 64 + u) * 768 + n0 + n] =
                    a * (1.f + g_mk[mg * 768 + n0 + n]);
            });
    }
    grid_bar(nb);

    // ---- S4: score partials, K split x3 (K=256): 384 tiles ----
    for (int tt = bid; tt < 384; tt += nb) {
        int kp = tt >> 7, lt = tt & 127;
        int b = lt >> 5, l2 = lt & 31;
        int m0 = (l2 & 7) * 64, n0 = (l2 >> 3) * 64, kb = kp * 256;
        gemm_block<true>(256, sA, sB,
            [&](int m, int k) { return ld4(&g_Ak[b * 393216 + (m0 + m) * 768 + kb + k]); },
            [&](int n, int k) { return ld4(&g_s[(b * 256 + n0 + n) * 768 + kb + k]); },
            [&](int m, int n, float a) {
                g_wp[kp * WP + b * 131072 + (m0 + m) * 256 + n0 + n] = a;
            });
    }
    grid_bar(nb);

    // ---- S5: softmax( (wp0+wp1+wp2+qbk)/8 ) -> g_w ----
    for (int r = wglob; r < 2048; r += nwarp) {
        int b = r >> 9, mg = r & 511;
        int h = mg >> 6, u = mg & 63;
        float qb = g_qbk[(b * 64 + u) * 8 + h];
        long base = (long)b * 131072 + (long)mg * 256;
        float v[8], mx = -1e30f;
        #pragma unroll
        for (int i = 0; i < 8; i++) {
            long idx = base + lane32 + 32 * i;
            v[i] = (g_wp[idx] + g_wp[WP + idx] + g_wp[2 * WP + idx] + qb) * 0.125f;
            mx = fmaxf(mx, v[i]);
        }
        #pragma unroll
        for (int off = 16; off; off >>= 1) mx = fmaxf(mx, __shfl_xor_sync(0xffffffffu, mx, off));
        float sm = 0.f;
        #pragma unroll
        for (int i = 0; i < 8; i++) { v[i] = expf(v[i] - mx); sm += v[i]; }
        #pragma unroll
        for (int off = 16; off; off >>= 1) sm += __shfl_xor_sync(0xffffffffu, sm, off);
        float inv = 1.f / sm;
        #pragma unroll
        for (int i = 0; i < 8; i++) g_w[base + lane32 + 32 * i] = v[i] * inv;
    }
    grid_bar(nb);

    // ---- S6: Tm = (w @ s)*(1+mv), per-head remap: 384 tiles, K=256 ----
    for (int tt = bid; tt < 384; tt += nb) {
        int b = tt / 96, lt = tt % 96;
        int m0 = (lt & 7) * 64, n0 = (lt >> 3) * 64;
        gemm_block<false>(256, sA, sB,
            [&](int m, int k) { return ld4(&g_w[b * 131072 + (m0 + m) * 256 + k]); },
            [&](int k, int n) { return ld4(&g_s[(b * 256 + k) * 768 + n0 + n]); },
            [&](int m, int n, float a) {
                int mg = m0 + m; int h = mg >> 6, u = mg & 63; int bu = b * 64 + u;
                g_Tm[(h * 256 + bu) * 768 + n0 + n] = a * (1.f + g_mv[bu * 768 + n0 + n]);
            });
    }
    grid_bar(nb);

    // ---- S7: msg partials = Tm_h @ Wv_h, K split x8 (K=96): 256 tiles ----
    for (int tt = bid; tt < 256; tt += nb) {
        int kp = tt >> 5, lt = tt & 31;
        int h = lt >> 2, m0 = (lt & 3) * 64, kb = kp * 96;
        gemm_block<false>(96, sA, sB,
            [&](int m, int k) { return ld4(&g_Tm[(h * 256 + m0 + m) * 768 + kb + k]); },
            [&](int k, int n) { return ld4(&P.Wv[(kb + k) * 512 + h * 64 + n]); },
            [&](int m, int n, float a) {
                g_qp[kp * QP + (m0 + m) * 512 + h * 64 + n] = a;
            });
    }
    grid_bar(nb);

    // ---- S7b: msg = (sum(8 partials)+bv)*(1+me) ----
    {
        int nth = nwarp * 32;
        int gt = wglob * 32 + lane32;
        for (int i = gt; i < 32768; i += nth) {
            long idx = (long)i * 4;
            int c = (int)(idx & 511);
            float4 acc = ld4(&P.bv[c]);
            #pragma unroll
            for (int p = 0; p < 8; p++) {
                float4 v = ld4(&g_qp[p * QP + idx]);
                acc.x += v.x; acc.y += v.y; acc.z += v.z; acc.w += v.w;
            }
            float4 me = ld4(&g_me[idx]);
            float4 o;
            o.x = acc.x * (1.f + me.x); o.y = acc.y * (1.f + me.y);
            o.z = acc.z * (1.f + me.z); o.w = acc.w * (1.f + me.w);
            *(float4*)&g_msg[idx] = o;
        }
    }
    grid_bar(nb);

    // ---- S8: out partials = msg @ We, K split x8 (K=64): 384 tiles ----
    for (int tt = bid; tt < 384; tt += nb) {
        int kp = tt / 48, lt = tt % 48;
        int m0 = (lt & 3) * 64, n0 = (lt >> 2) * 64, kb = kp * 64;
        gemm_block<false>(64, sA, sB,
            [&](int m, int k) { return ld4(&g_msg[(m0 + m) * 512 + kb + k]); },
            [&](int k, int n) { return ld4(&P.We[(kb + k) * 768 + n0 + n]); },
            [&](int m, int n, float a) {
                g_wp[kp * OP + (m0 + m) * 768 + n0 + n] = a;
            });
    }
    grid_bar(nb);

    // ---- S9: out = recv + (sum(8 partials)+be)*gamma ----
    {
        int nth = nwarp * 32;
        int gt = wglob * 32 + lane32;
        for (int i = gt; i < 49152; i += nth) {
            long idx = (long)i * 4;
            int c = (int)(idx % 768);
            float4 acc = ld4(&P.be[c]);
            #pragma unroll
            for (int p = 0; p < 8; p++) {
                float4 v = ld4(&g_wp[p * OP + idx]);
                acc.x += v.x; acc.y += v.y; acc.z += v.z; acc.w += v.w;
            }
            float4 ga = ld4(&P.gamma[c]);
            float4 rv = ld4(&P.recv[idx]);
            float4 o;
            o.x = rv.x + acc.x * ga.x; o.y = rv.y + acc.y * ga.y;
            o.z = rv.z + acc.z * ga.z; o.w = rv.w + acc.w * ga.w;
            *(float4*)&P.out[idx] = o;
        }
    }
}

// ---------------- Host launcher ----------------
extern "C" void kernel_launch(void* const* d_in, const int* in_sizes, int n_in,
                              void* d_out, int out_size) {
    (void)in_sizes; (void)n_in; (void)out_size;
    Params P;
    P.recv  = (const float*)d_in[0];
    P.codes = (const float*)d_in[1];
    P.send  = (const float*)d_in[2];
    P.lnrg  = (const float*)d_in[3];
    P.lnrb  = (const float*)d_in[4];
    P.lnsg  = (const float*)d_in[5];
    P.lnsb  = (const float*)d_in[6];
    P.Wq  = (const float*)d_in[7];
    P.bq  = (const float*)d_in[8];
    P.Wmq = (const float*)d_in[9];
    P.Wk  = (const float*)d_in[10];
    P.bk  = (const float*)d_in[11];
    P.Wmk = (const float*)d_in[12];
    P.Wv  = (const float*)d_in[13];
    P.bv  = (const float*)d_in[14];
    P.Wmv = (const float*)d_in[15];
    P.We  = (const float*)d_in[16];
    P.be  = (const float*)d_in[17];
    P.Wme = (const float*)d_in[18];
    P.gamma = (const float*)d_in[19];
    P.out = (float*)d_out;

    int occ = 0;
    cudaOccupancyMaxActiveBlocksPerMultiprocessor(&occ, fused_kernel, TPB, 0);
    if (occ < 1) occ = 1;
    int dev = 0;
    cudaGetDevice(&dev);
    int sms = 0;
    cudaDeviceGetAttribute(&sms, cudaDevAttrMultiProcessorCount, dev);
    if (sms < 1) sms = 1;
    int nb = occ * sms;
    if (nb > 1024) nb = 1024;
    P.nb = nb;

    fused_kernel<<<nb, TPB>>>(P);
}

// round 9
// speedup vs baseline: 2.9993x; 1.0875x over previous
#include <cuda_runtime.h>
#include <cstdint>

#define TPB 256
#define SAS 20
#define SBSN 72
#define ABUF 1280          // 64*20 words per stage
#define BBUF 1280          // max(16*72=1152, 64*20=1280)

// B=4, U=64, V=256, DIM=768, CODE=384, INNER=512, HEADS=8, HD=64

struct Params {
    const float *recv, *codes, *send;
    const float *lnrg, *lnrb, *lnsg, *lnsb;
    const float *Wq, *bq, *Wmq, *Wk, *bk, *Wmk;
    const float *Wv, *bv, *Wmv, *We, *be, *Wme, *gamma;
    float* out;
    int nb;
};

// ---------------- Scratch (device globals; no allocs) ----------------
__device__ __align__(16) float g_r  [256 * 768];
__device__ __align__(16) float g_s  [1024 * 768];
__device__ __align__(16) float g_rq [256 * 768];   // r*(1+mq), via S1 epilogue
__device__ __align__(16) float g_mk [256 * 768];
__device__ __align__(16) float g_mv [256 * 768];
__device__ __align__(16) float g_me [256 * 512];
__device__ __align__(16) float g_q  [256 * 512];
__device__ __align__(16) float g_qbk[256 * 8];
__device__ __align__(16) float g_Ak [4 * 512 * 768];
__device__ __align__(16) float g_w  [4 * 512 * 256];
__device__ __align__(16) float g_Tm [8 * 256 * 768];
__device__ __align__(16) float g_msg[256 * 512];
#define QP 131072      // 256*512
#define WP 524288      // 4*512*256
#define OP 196608      // 256*768
__device__ __align__(16) float g_qp[8 * QP];   // q partials; reused as msg partials
__device__ __align__(16) float g_wp[3 * WP];   // score partials (3); reused as 8 out partials

__device__ unsigned g_barcnt = 0;
__device__ unsigned g_bargen = 0;

__device__ __forceinline__ void grid_bar(int nb) {
    __syncthreads();
    if (threadIdx.x == 0) {
        __threadfence();
        unsigned gen = *(volatile unsigned*)&g_bargen;
        unsigned t = atomicAdd(&g_barcnt, 1u);
        if (t == (unsigned)(nb - 1)) {
            atomicExch(&g_barcnt, 0u);
            __threadfence();
            atomicExch(&g_bargen, gen + 1u);
        } else {
            while (*(volatile unsigned*)&g_bargen == gen) { __nanosleep(32); }
        }
        __threadfence();
    }
    __syncthreads();
}

// ---------------- mma + cp.async helpers ----------------
__device__ __forceinline__ void mma8(float* c, const uint32_t* a, const uint32_t* b) {
    asm volatile(
        "mma.sync.aligned.m16n8k8.row.col.f32.tf32.tf32.f32 "
        "{%0,%1,%2,%3}, {%4,%5,%6,%7}, {%8,%9}, {%0,%1,%2,%3};"
        : "+f"(c[0]), "+f"(c[1]), "+f"(c[2]), "+f"(c[3])
        : "r"(a[0]), "r"(a[1]), "r"(a[2]), "r"(a[3]), "r"(b[0]), "r"(b[1]));
}
// round-to-nearest tf32 conversion of a raw fp32 bit pattern
__device__ __forceinline__ uint32_t tfr(uint32_t raw) {
    uint32_t u;
    asm("cvt.rna.tf32.f32 %0, %1;" : "=r"(u) : "f"(__uint_as_float(raw)));
    return u;
}
__device__ __forceinline__ void cp16(uint32_t dst, const float* src) {
    asm volatile("cp.async.cg.shared.global [%0], [%1], 16;\n"
                 :: "r"(dst), "l"(src) : "memory");
}
__device__ __forceinline__ void cp_commit() {
    asm volatile("cp.async.commit_group;\n" ::: "memory");
}
__device__ __forceinline__ void cp_wait2() {
    asm volatile("cp.async.wait_group 2;\n" ::: "memory");
}

// ------- block 64x64 tf32 GEMM, 4-stage cp.async pipeline, rna at frag load -------
// C(m,n) = sum_k A(m,k)*B(k,n); K%16==0, K>=64.
// la(m,k)->ptr to A(m,k..k+3). BT=false: lb(k,n)->ptr B(k,n..n+3);
// BT=true: lb(n,k)->ptr B(n-th row, k..k+3)  (smem stored [n][k]).
template<bool BT, class LA, class LB, class EP>
__device__ __forceinline__ void gemm_cp(int K, uint32_t* sA, uint32_t* sB,
                                        uint32_t saA, uint32_t saB,
                                        LA la, LB lb, EP ep) {
    const int tid = threadIdx.x;
    const int l = tid & 31, g = l >> 2, t = l & 3;
    const int wid = tid >> 5;
    const int wm0 = (wid & 1) * 32, wn0 = (wid >> 1) * 16;
    const int am = tid >> 2, ak = (tid & 3) * 4;
    const int bk = tid >> 4, bn = (tid & 15) * 4;
    const int btn = tid >> 2, btk = (tid & 3) * 4;
    const int ns = K / 16;

    const uint32_t dA = saA + (uint32_t)(am * SAS + ak) * 4u;
    const uint32_t dB = BT ? saB + (uint32_t)(btn * SAS + btk) * 4u
                           : saB + (uint32_t)(bk * SBSN + bn) * 4u;

    auto issue = [&](int s) {
        int buf = s & 3;
        int k0 = s * 16;
        cp16(dA + buf * (ABUF * 4), la(am, k0 + ak));
        // FIX vs R6/R7: NN mode k-offset belongs on the K argument, not N.
        cp16(dB + buf * (BBUF * 4), BT ? lb(btn, k0 + btk) : lb(k0 + bk, bn));
        cp_commit();
    };

    float acc[2][2][4];
    #pragma unroll
    for (int i = 0; i < 2; i++)
        #pragma unroll
        for (int j = 0; j < 2; j++)
            #pragma unroll
            for (int e = 0; e < 4; e++) acc[i][j][e] = 0.f;

    issue(0); issue(1); issue(2);
    cp_wait2();
    __syncthreads();

    for (int s = 0; s < ns; s++) {
        const uint32_t* __restrict__ A = sA + (s & 3) * ABUF;
        const uint32_t* __restrict__ B = sB + (s & 3) * BBUF;
        #pragma unroll
        for (int kk = 0; kk < 16; kk += 8) {
            uint32_t af[2][4], bf[2][2];
            #pragma unroll
            for (int mi = 0; mi < 2; mi++) {
                int mb = wm0 + mi * 16;
                af[mi][0] = tfr(A[(mb + g) * SAS + kk + t]);
                af[mi][1] = tfr(A[(mb + 8 + g) * SAS + kk + t]);
                af[mi][2] = tfr(A[(mb + g) * SAS + kk + t + 4]);
                af[mi][3] = tfr(A[(mb + 8 + g) * SAS + kk + t + 4]);
            }
            #pragma unroll
            for (int ni = 0; ni < 2; ni++) {
                int nn = wn0 + ni * 8 + g;
                if (BT) {
                    bf[ni][0] = tfr(B[nn * SAS + kk + t]);
                    bf[ni][1] = tfr(B[nn * SAS + kk + t + 4]);
                } else {
                    bf[ni][0] = tfr(B[(kk + t) * SBSN + nn]);
                    bf[ni][1] = tfr(B[(kk + t + 4) * SBSN + nn]);
                }
            }
            #pragma unroll
            for (int mi = 0; mi < 2; mi++)
                #pragma unroll
                for (int ni = 0; ni < 2; ni++)
                    mma8(acc[mi][ni], af[mi], bf[ni]);
        }
        __syncthreads();
        if (s + 3 < ns) issue(s + 3); else cp_commit();
        cp_wait2();
        __syncthreads();
    }

    #pragma unroll
    for (int mi = 0; mi < 2; mi++)
        #pragma unroll
        for (int ni = 0; ni < 2; ni++) {
            int r = wm0 + mi * 16 + g, c = wn0 + ni * 8 + 2 * t;
            ep(r,     c,     acc[mi][ni][0]);
            ep(r,     c + 1, acc[mi][ni][1]);
            ep(r + 8, c,     acc[mi][ni][2]);
            ep(r + 8, c + 1, acc[mi][ni][3]);
        }
}

__device__ __forceinline__ float4 ld4(const float* p) { return *(const float4*)p; }

// ---------------- warp LayerNorm over a 768-row ----------------
__device__ __forceinline__ void ln_row(const float* __restrict__ x,
                                       const float* __restrict__ g,
                                       const float* __restrict__ b,
                                       float* __restrict__ o) {
    int lane = threadIdx.x & 31;
    float v[24];
    float s = 0.f, q = 0.f;
    #pragma unroll
    for (int i = 0; i < 24; i++) {
        v[i] = x[lane + 32 * i];
        s += v[i];
        q += v[i] * v[i];
    }
    #pragma unroll
    for (int off = 16; off; off >>= 1) {
        s += __shfl_xor_sync(0xffffffffu, s, off);
        q += __shfl_xor_sync(0xffffffffu, q, off);
    }
    float mu  = s * (1.f / 768.f);
    float inv = rsqrtf(q * (1.f / 768.f) - mu * mu + 1e-5f);
    #pragma unroll
    for (int i = 0; i < 24; i++) {
        int idx = lane + 32 * i;
        o[idx] = (v[i] - mu) * inv * g[idx] + b[idx];
    }
}

// ---------------- The single persistent kernel ----------------
__global__ void __launch_bounds__(TPB, 3) fused_kernel(Params P) {
    __shared__ __align__(16) uint32_t sA[4 * ABUF];
    __shared__ __align__(16) uint32_t sB[4 * BBUF];
    const uint32_t saA = (uint32_t)__cvta_generic_to_shared(sA);
    const uint32_t saB = (uint32_t)__cvta_generic_to_shared(sB);
    const int nb = P.nb;
    const int bid = blockIdx.x;
    const int wglob = bid * 8 + (threadIdx.x >> 5);
    const int nwarp = nb * 8;
    const int lane32 = threadIdx.x & 31;

    // ---- S0: LayerNorms ----
    for (int r = wglob; r < 1280; r += nwarp) {
        if (r < 256) ln_row(P.recv + r * 768, P.lnrg, P.lnrb, g_r + r * 768);
        else {
            int rr = r - 256;
            ln_row(P.send + rr * 768, P.lnsg, P.lnsb, g_s + rr * 768);
        }
    }
    grid_bar(nb);

    // ---- S1: 4 modulation GEMMs; mq-tiles write rq = r*(1+mq) ----
    for (int tt = bid; tt < 176; tt += nb) {
        const float* W; float* O; int N; int lt; int mode;
        if (tt < 144) {
            int sel = tt / 48; lt = tt % 48; N = 768;
            W = sel == 0 ? P.Wmq : (sel == 1 ? P.Wmk : P.Wmv);
            O = sel == 0 ? g_rq : (sel == 1 ? g_mk : g_mv);
            mode = (sel == 0) ? 0 : 1;
        } else { lt = tt - 144; W = P.Wme; O = g_me; N = 512; mode = 1; }
        int m0 = (lt & 3) * 64, n0 = (lt >> 2) * 64;
        gemm_cp<false>(384, sA, sB, saA, saB,
            [&](int m, int k) { return &P.codes[(m0 + m) * 384 + k]; },
            [&](int k, int n) { return &W[k * N + n0 + n]; },
            [&](int m, int n, float a) {
                long o = (long)(m0 + m) * N + n0 + n;
                if (mode == 0) O[o] = g_r[o] * (1.f + a);
                else O[o] = a;
            });
    }
    grid_bar(nb);

    // ---- S2: q partials, K split x8 (K=96): 256 tiles ----
    for (int tt = bid; tt < 256; tt += nb) {
        int kp = tt >> 5, lt = tt & 31;
        int m0 = (lt & 3) * 64, n0 = (lt >> 2) * 64, kb = kp * 96;
        gemm_cp<false>(96, sA, sB, saA, saB,
            [&](int m, int k) { return &g_rq[(m0 + m) * 768 + kb + k]; },
            [&](int k, int n) { return &P.Wq[(kb + k) * 512 + n0 + n]; },
            [&](int m, int n, float a) { g_qp[kp * QP + (m0 + m) * 512 + n0 + n] = a; });
    }
    grid_bar(nb);

    // ---- S2b: q = sum(8 partials)+bq ; qbk = q_h . bk_h ----
    for (int w = wglob; w < 2048; w += nwarp) {
        int bu = w >> 3, h = w & 7;
        int base = bu * 512 + h * 64;
        int c0 = h * 64 + lane32, c1 = c0 + 32;
        float q0 = P.bq[c0], q1 = P.bq[c1];
        #pragma unroll
        for (int p = 0; p < 8; p++) {
            q0 += g_qp[p * QP + base + lane32];
            q1 += g_qp[p * QP + base + lane32 + 32];
        }
        g_q[base + lane32] = q0;
        g_q[base + lane32 + 32] = q1;
        float s = q0 * P.bk[c0] + q1 * P.bk[c1];
        #pragma unroll
        for (int off = 16; off; off >>= 1) s += __shfl_xor_sync(0xffffffffu, s, off);
        if (lane32 == 0) g_qbk[bu * 8 + h] = s;
    }
    grid_bar(nb);

    // ---- S3: Ak = (Wk_h^T q_h)*(1+mk)  per-head NT, K=64: 384 tiles ----
    for (int tt = bid; tt < 384; tt += nb) {
        int h = tt / 48, lt = tt % 48;
        int m0 = (lt & 3) * 64, n0 = (lt >> 2) * 64;
        gemm_cp<true>(64, sA, sB, saA, saB,
            [&](int m, int k) { return &g_q[(m0 + m) * 512 + h * 64 + k]; },
            [&](int n, int k) { return &P.Wk[(n0 + n) * 512 + h * 64 + k]; },
            [&](int m, int n, float a) {
                int mg = m0 + m; int b = mg >> 6, u = mg & 63;
                g_Ak[b * 393216 + (h * 64 + u) * 768 + n0 + n] =
                    a * (1.f + g_mk[mg * 768 + n0 + n]);
            });
    }
    grid_bar(nb);

    // ---- S4: score partials, K split x3 (K=256): 384 tiles ----
    for (int tt = bid; tt < 384; tt += nb) {
        int kp = tt >> 7, lt = tt & 127;
        int b = lt >> 5, l2 = lt & 31;
        int m0 = (l2 & 7) * 64, n0 = (l2 >> 3) * 64, kb = kp * 256;
        gemm_cp<true>(256, sA, sB, saA, saB,
            [&](int m, int k) { return &g_Ak[b * 393216 + (m0 + m) * 768 + kb + k]; },
            [&](int n, int k) { return &g_s[(b * 256 + n0 + n) * 768 + kb + k]; },
            [&](int m, int n, float a) {
                g_wp[kp * WP + b * 131072 + (m0 + m) * 256 + n0 + n] = a;
            });
    }
    grid_bar(nb);

    // ---- S5: softmax( (wp0+wp1+wp2+qbk)/8 ) -> g_w ----
    for (int r = wglob; r < 2048; r += nwarp) {
        int b = r >> 9, mg = r & 511;
        int h = mg >> 6, u = mg & 63;
        float qb = g_qbk[(b * 64 + u) * 8 + h];
        long base = (long)b * 131072 + (long)mg * 256;
        float v[8], mx = -1e30f;
        #pragma unroll
        for (int i = 0; i < 8; i++) {
            long idx = base + lane32 + 32 * i;
            v[i] = (g_wp[idx] + g_wp[WP + idx] + g_wp[2 * WP + idx] + qb) * 0.125f;
            mx = fmaxf(mx, v[i]);
        }
        #pragma unroll
        for (int off = 16; off; off >>= 1) mx = fmaxf(mx, __shfl_xor_sync(0xffffffffu, mx, off));
        float sm = 0.f;
        #pragma unroll
        for (int i = 0; i < 8; i++) { v[i] = expf(v[i] - mx); sm += v[i]; }
        #pragma unroll
        for (int off = 16; off; off >>= 1) sm += __shfl_xor_sync(0xffffffffu, sm, off);
        float inv = 1.f / sm;
        #pragma unroll
        for (int i = 0; i < 8; i++) g_w[base + lane32 + 32 * i] = v[i] * inv;
    }
    grid_bar(nb);

    // ---- S6: Tm = (w @ s)*(1+mv), per-head remap: 384 tiles, K=256 ----
    for (int tt = bid; tt < 384; tt += nb) {
        int b = tt / 96, lt = tt % 96;
        int m0 = (lt & 7) * 64, n0 = (lt >> 3) * 64;
        gemm_cp<false>(256, sA, sB, saA, saB,
            [&](int m, int k) { return &g_w[b * 131072 + (m0 + m) * 256 + k]; },
            [&](int k, int n) { return &g_s[(b * 256 + k) * 768 + n0 + n]; },
            [&](int m, int n, float a) {
                int mg = m0 + m; int h = mg >> 6, u = mg & 63; int bu = b * 64 + u;
                g_Tm[(h * 256 + bu) * 768 + n0 + n] = a * (1.f + g_mv[bu * 768 + n0 + n]);
            });
    }
    grid_bar(nb);

    // ---- S7: msg partials = Tm_h @ Wv_h, K split x8 (K=96): 256 tiles ----
    for (int tt = bid; tt < 256; tt += nb) {
        int kp = tt >> 5, lt = tt & 31;
        int h = lt >> 2, m0 = (lt & 3) * 64, kb = kp * 96;
        gemm_cp<false>(96, sA, sB, saA, saB,
            [&](int m, int k) { return &g_Tm[(h * 256 + m0 + m) * 768 + kb + k]; },
            [&](int k, int n) { return &P.Wv[(kb + k) * 512 + h * 64 + n]; },
            [&](int m, int n, float a) {
                g_qp[kp * QP + (m0 + m) * 512 + h * 64 + n] = a;
            });
    }
    grid_bar(nb);

    // ---- S7b: msg = (sum(8 partials)+bv)*(1+me) ----
    {
        int nth = nwarp * 32;
        int gt = wglob * 32 + lane32;
        for (int i = gt; i < 32768; i += nth) {
            long idx = (long)i * 4;
            int c = (int)(idx & 511);
            float4 acc = ld4(&P.bv[c]);
            #pragma unroll
            for (int p = 0; p < 8; p++) {
                float4 v = ld4(&g_qp[p * QP + idx]);
                acc.x += v.x; acc.y += v.y; acc.z += v.z; acc.w += v.w;
            }
            float4 me = ld4(&g_me[idx]);
            float4 o;
            o.x = acc.x * (1.f + me.x); o.y = acc.y * (1.f + me.y);
            o.z = acc.z * (1.f + me.z); o.w = acc.w * (1.f + me.w);
            *(float4*)&g_msg[idx] = o;
        }
    }
    grid_bar(nb);

    // ---- S8: out partials = msg @ We, K split x8 (K=64): 384 tiles ----
    for (int tt = bid; tt < 384; tt += nb) {
        int kp = tt / 48, lt = tt % 48;
        int m0 = (lt & 3) * 64, n0 = (lt >> 2) * 64, kb = kp * 64;
        gemm_cp<false>(64, sA, sB, saA, saB,
            [&](int m, int k) { return &g_msg[(m0 + m) * 512 + kb + k]; },
            [&](int k, int n) { return &P.We[(kb + k) * 768 + n0 + n]; },
            [&](int m, int n, float a) {
                g_wp[kp * OP + (m0 + m) * 768 + n0 + n] = a;
            });
    }
    grid_bar(nb);

    // ---- S9: out = recv + (sum(8 partials)+be)*gamma ----
    {
        int nth = nwarp * 32;
        int gt = wglob * 32 + lane32;
        for (int i = gt; i < 49152; i += nth) {
            long idx = (long)i * 4;
            int c = (int)(idx % 768);
            float4 acc = ld4(&P.be[c]);
            #pragma unroll
            for (int p = 0; p < 8; p++) {
                float4 v = ld4(&g_wp[p * OP + idx]);
                acc.x += v.x; acc.y += v.y; acc.z += v.z; acc.w += v.w;
            }
            float4 ga = ld4(&P.gamma[c]);
            float4 rv = ld4(&P.recv[idx]);
            float4 o;
            o.x = rv.x + acc.x * ga.x; o.y = rv.y + acc.y * ga.y;
            o.z = rv.z + acc.z * ga.z; o.w = rv.w + acc.w * ga.w;
            *(float4*)&P.out[idx] = o;
        }
    }
}

// ---------------- Host launcher ----------------
extern "C" void kernel_launch(void* const* d_in, const int* in_sizes, int n_in,
                              void* d_out, int out_size) {
    (void)in_sizes; (void)n_in; (void)out_size;
    Params P;
    P.recv  = (const float*)d_in[0];
    P.codes = (const float*)d_in[1];
    P.send  = (const float*)d_in[2];
    P.lnrg  = (const float*)d_in[3];
    P.lnrb  = (const float*)d_in[4];
    P.lnsg  = (const float*)d_in[5];
    P.lnsb  = (const float*)d_in[6];
    P.Wq  = (const float*)d_in[7];
    P.bq  = (const float*)d_in[8];
    P.Wmq = (const float*)d_in[9];
    P.Wk  = (const float*)d_in[10];
    P.bk  = (const float*)d_in[11];
    P.Wmk = (const float*)d_in[12];
    P.Wv  = (const float*)d_in[13];
    P.bv  = (const float*)d_in[14];
    P.Wmv = (const float*)d_in[15];
    P.We  = (const float*)d_in[16];
    P.be  = (const float*)d_in[17];
    P.Wme = (const float*)d_in[18];
    P.gamma = (const float*)d_in[19];
    P.out = (float*)d_out;

    int occ = 0;
    cudaOccupancyMaxActiveBlocksPerMultiprocessor(&occ, fused_kernel, TPB, 0);
    if (occ < 1) occ = 1;
    int dev = 0;
    cudaGetDevice(&dev);
    int sms = 0;
    cudaDeviceGetAttribute(&sms, cudaDevAttrMultiProcessorCount, dev);
    if (sms < 1) sms = 1;
    int nb = occ * sms;
    if (nb > 1024) nb = 1024;
    P.nb = nb;

    fused_kernel<<<nb, TPB>>>(P);
}

// round 10
// speedup vs baseline: 3.0043x; 1.0017x over previous
#include <cuda_runtime.h>
#include <cstdint>

#define TPB 256
#define SAS 20
#define SBSN 72
#define ABUF 1280          // 64*20 words per stage
#define BBUF 1280          // max(16*72=1152, 64*20=1280)

// B=4, U=64, V=256, DIM=768, CODE=384, INNER=512, HEADS=8, HD=64

struct Params {
    const float *recv, *codes, *send;
    const float *lnrg, *lnrb, *lnsg, *lnsb;
    const float *Wq, *bq, *Wmq, *Wk, *bk, *Wmk;
    const float *Wv, *bv, *Wmv, *We, *be, *Wme, *gamma;
    float* out;
    int nb;
};

// ---------------- Scratch (device globals; no allocs) ----------------
__device__ __align__(16) float g_r  [256 * 768];
__device__ __align__(16) float g_s  [1024 * 768];
__device__ __align__(16) float g_rq [256 * 768];      // r*(1+mq), via S1b merge
__device__ __align__(16) float g_mqp[2 * 196608];     // mq partials (K-split x2)
__device__ __align__(16) float g_mkp[2 * 196608];     // mk partials
__device__ __align__(16) float g_mvp[2 * 196608];     // mv partials
__device__ __align__(16) float g_mep[2 * 131072];     // me partials
__device__ __align__(16) float g_q  [256 * 512];
__device__ __align__(16) float g_qbk[256 * 8];
__device__ __align__(16) float g_Ak [4 * 512 * 768];
__device__ __align__(16) float g_w  [4 * 512 * 256];
__device__ __align__(16) float g_Tm [8 * 256 * 768];
__device__ __align__(16) float g_msg[256 * 512];
#define QP 131072      // 256*512
#define WP 524288      // 4*512*256
#define OP 196608      // 256*768
__device__ __align__(16) float g_qp[8 * QP];   // q partials; reused as msg partials
__device__ __align__(16) float g_wp[3 * WP];   // score partials (3); reused as 8 out partials

__device__ unsigned g_barcnt = 0;
__device__ unsigned g_bargen = 0;

__device__ __forceinline__ void grid_bar(int nb) {
    __syncthreads();
    if (threadIdx.x == 0) {
        __threadfence();
        unsigned gen = *(volatile unsigned*)&g_bargen;
        unsigned t = atomicAdd(&g_barcnt, 1u);
        if (t == (unsigned)(nb - 1)) {
            atomicExch(&g_barcnt, 0u);
            __threadfence();
            atomicExch(&g_bargen, gen + 1u);
        } else {
            while (*(volatile unsigned*)&g_bargen == gen) { __nanosleep(32); }
        }
        __threadfence();
    }
    __syncthreads();
}

// ---------------- mma + cp.async helpers ----------------
__device__ __forceinline__ void mma8(float* c, const uint32_t* a, const uint32_t* b) {
    asm volatile(
        "mma.sync.aligned.m16n8k8.row.col.f32.tf32.tf32.f32 "
        "{%0,%1,%2,%3}, {%4,%5,%6,%7}, {%8,%9}, {%0,%1,%2,%3};"
        : "+f"(c[0]), "+f"(c[1]), "+f"(c[2]), "+f"(c[3])
        : "r"(a[0]), "r"(a[1]), "r"(a[2]), "r"(a[3]), "r"(b[0]), "r"(b[1]));
}
__device__ __forceinline__ uint32_t tfr(uint32_t raw) {
    uint32_t u;
    asm("cvt.rna.tf32.f32 %0, %1;" : "=r"(u) : "f"(__uint_as_float(raw)));
    return u;
}
__device__ __forceinline__ void cp16(uint32_t dst, const float* src) {
    asm volatile("cp.async.cg.shared.global [%0], [%1], 16;\n"
                 :: "r"(dst), "l"(src) : "memory");
}
__device__ __forceinline__ void cp_commit() {
    asm volatile("cp.async.commit_group;\n" ::: "memory");
}
__device__ __forceinline__ void cp_wait2() {
    asm volatile("cp.async.wait_group 2;\n" ::: "memory");
}

// ------- block 64x64 tf32 GEMM, 4-stage cp.async pipeline, single sync/step -------
// C(m,n) = sum_k A(m,k)*B(k,n); K%16==0, K>=64.
template<bool BT, class LA, class LB, class EP>
__device__ __forceinline__ void gemm_cp(int K, uint32_t* sA, uint32_t* sB,
                                        uint32_t saA, uint32_t saB,
                                        LA la, LB lb, EP ep) {
    const int tid = threadIdx.x;
    const int l = tid & 31, g = l >> 2, t = l & 3;
    const int wid = tid >> 5;
    const int wm0 = (wid & 1) * 32, wn0 = (wid >> 1) * 16;
    const int am = tid >> 2, ak = (tid & 3) * 4;
    const int bk = tid >> 4, bn = (tid & 15) * 4;
    const int btn = tid >> 2, btk = (tid & 3) * 4;
    const int ns = K / 16;

    const uint32_t dA = saA + (uint32_t)(am * SAS + ak) * 4u;
    const uint32_t dB = BT ? saB + (uint32_t)(btn * SAS + btk) * 4u
                           : saB + (uint32_t)(bk * SBSN + bn) * 4u;

    auto issue = [&](int s) {
        int buf = s & 3;
        int k0 = s * 16;
        cp16(dA + buf * (ABUF * 4), la(am, k0 + ak));
        cp16(dB + buf * (BBUF * 4), BT ? lb(btn, k0 + btk) : lb(k0 + bk, bn));
        cp_commit();
    };

    float acc[2][2][4];
    #pragma unroll
    for (int i = 0; i < 2; i++)
        #pragma unroll
        for (int j = 0; j < 2; j++)
            #pragma unroll
            for (int e = 0; e < 4; e++) acc[i][j][e] = 0.f;

    issue(0); issue(1); issue(2);
    cp_wait2();
    __syncthreads();

    for (int s = 0; s < ns; s++) {
        // Issue for step s+3 FIRST: overwrites buf (s-1)&3, which every warp
        // finished reading before the sync at the end of step s-1.
        if (s + 3 < ns) issue(s + 3); else cp_commit();
        const uint32_t* __restrict__ A = sA + (s & 3) * ABUF;
        const uint32_t* __restrict__ B = sB + (s & 3) * BBUF;
        #pragma unroll
        for (int kk = 0; kk < 16; kk += 8) {
            uint32_t af[2][4], bf[2][2];
            #pragma unroll
            for (int mi = 0; mi < 2; mi++) {
                int mb = wm0 + mi * 16;
                af[mi][0] = tfr(A[(mb + g) * SAS + kk + t]);
                af[mi][1] = tfr(A[(mb + 8 + g) * SAS + kk + t]);
                af[mi][2] = tfr(A[(mb + g) * SAS + kk + t + 4]);
                af[mi][3] = tfr(A[(mb + 8 + g) * SAS + kk + t + 4]);
            }
            #pragma unroll
            for (int ni = 0; ni < 2; ni++) {
                int nn = wn0 + ni * 8 + g;
                if (BT) {
                    bf[ni][0] = tfr(B[nn * SAS + kk + t]);
                    bf[ni][1] = tfr(B[nn * SAS + kk + t + 4]);
                } else {
                    bf[ni][0] = tfr(B[(kk + t) * SBSN + nn]);
                    bf[ni][1] = tfr(B[(kk + t + 4) * SBSN + nn]);
                }
            }
            #pragma unroll
            for (int mi = 0; mi < 2; mi++)
                #pragma unroll
                for (int ni = 0; ni < 2; ni++)
                    mma8(acc[mi][ni], af[mi], bf[ni]);
        }
        cp_wait2();
        __syncthreads();
    }

    #pragma unroll
    for (int mi = 0; mi < 2; mi++)
        #pragma unroll
        for (int ni = 0; ni < 2; ni++) {
            int r = wm0 + mi * 16 + g, c = wn0 + ni * 8 + 2 * t;
            ep(r,     c,     acc[mi][ni][0]);
            ep(r,     c + 1, acc[mi][ni][1]);
            ep(r + 8, c,     acc[mi][ni][2]);
            ep(r + 8, c + 1, acc[mi][ni][3]);
        }
}

__device__ __forceinline__ float4 ld4(const float* p) { return *(const float4*)p; }

// ---------------- warp LayerNorm over a 768-row ----------------
__device__ __forceinline__ void ln_row(const float* __restrict__ x,
                                       const float* __restrict__ g,
                                       const float* __restrict__ b,
                                       float* __restrict__ o) {
    int lane = threadIdx.x & 31;
    float v[24];
    float s = 0.f, q = 0.f;
    #pragma unroll
    for (int i = 0; i < 24; i++) {
        v[i] = x[lane + 32 * i];
        s += v[i];
        q += v[i] * v[i];
    }
    #pragma unroll
    for (int off = 16; off; off >>= 1) {
        s += __shfl_xor_sync(0xffffffffu, s, off);
        q += __shfl_xor_sync(0xffffffffu, q, off);
    }
    float mu  = s * (1.f / 768.f);
    float inv = rsqrtf(q * (1.f / 768.f) - mu * mu + 1e-5f);
    #pragma unroll
    for (int i = 0; i < 24; i++) {
        int idx = lane + 32 * i;
        o[idx] = (v[i] - mu) * inv * g[idx] + b[idx];
    }
}

// ---------------- The single persistent kernel ----------------
__global__ void __launch_bounds__(TPB, 3) fused_kernel(Params P) {
    __shared__ __align__(16) uint32_t sA[4 * ABUF];
    __shared__ __align__(16) uint32_t sB[4 * BBUF];
    const uint32_t saA = (uint32_t)__cvta_generic_to_shared(sA);
    const uint32_t saB = (uint32_t)__cvta_generic_to_shared(sB);
    const int nb = P.nb;
    const int bid = blockIdx.x;
    const int wglob = bid * 8 + (threadIdx.x >> 5);
    const int nwarp = nb * 8;
    const int lane32 = threadIdx.x & 31;
    const int nth = nwarp * 32;
    const int gt = wglob * 32 + lane32;

    // ---- S0: LayerNorms ----
    for (int r = wglob; r < 1280; r += nwarp) {
        if (r < 256) ln_row(P.recv + r * 768, P.lnrg, P.lnrb, g_r + r * 768);
        else {
            int rr = r - 256;
            ln_row(P.send + rr * 768, P.lnsg, P.lnsb, g_s + rr * 768);
        }
    }
    grid_bar(nb);

    // ---- S1: 4 modulation GEMMs, K split x2 (K=192): 352 tiles, 12 steps ----
    for (int tt = bid; tt < 352; tt += nb) {
        const float* W; float* O; int N, lt, kp;
        if (tt < 288) {
            int sel = tt / 96, r = tt % 96;
            kp = r / 48; lt = r % 48; N = 768;
            W = sel == 0 ? P.Wmq : (sel == 1 ? P.Wmk : P.Wmv);
            O = (sel == 0 ? g_mqp : (sel == 1 ? g_mkp : g_mvp)) + kp * 196608;
        } else {
            int r = tt - 288;
            kp = r / 32; lt = r % 32; N = 512;
            W = P.Wme; O = g_mep + kp * 131072;
        }
        int m0 = (lt & 3) * 64, n0 = (lt >> 2) * 64, kb = kp * 192;
        gemm_cp<false>(192, sA, sB, saA, saB,
            [&](int m, int k) { return &P.codes[(m0 + m) * 384 + kb + k]; },
            [&](int k, int n) { return &W[(kb + k) * N + n0 + n]; },
            [&](int m, int n, float a) { O[(long)(m0 + m) * N + n0 + n] = a; });
    }
    grid_bar(nb);

    // ---- S1b: rq = r * (1 + mqp0 + mqp1) ----
    for (int i = gt; i < 49152; i += nth) {   // 196608/4
        long idx = (long)i * 4;
        float4 a = ld4(&g_mqp[idx]), b = ld4(&g_mqp[196608 + idx]), r = ld4(&g_r[idx]);
        float4 o;
        o.x = r.x * (1.f + a.x + b.x); o.y = r.y * (1.f + a.y + b.y);
        o.z = r.z * (1.f + a.z + b.z); o.w = r.w * (1.f + a.w + b.w);
        *(float4*)&g_rq[idx] = o;
    }
    grid_bar(nb);

    // ---- S2: q partials, K split x8 (K=96): 256 tiles ----
    for (int tt = bid; tt < 256; tt += nb) {
        int kp = tt >> 5, lt = tt & 31;
        int m0 = (lt & 3) * 64, n0 = (lt >> 2) * 64, kb = kp * 96;
        gemm_cp<false>(96, sA, sB, saA, saB,
            [&](int m, int k) { return &g_rq[(m0 + m) * 768 + kb + k]; },
            [&](int k, int n) { return &P.Wq[(kb + k) * 512 + n0 + n]; },
            [&](int m, int n, float a) { g_qp[kp * QP + (m0 + m) * 512 + n0 + n] = a; });
    }
    grid_bar(nb);

    // ---- S2b: q = sum(8 partials)+bq ; qbk = q_h . bk_h ----
    for (int w = wglob; w < 2048; w += nwarp) {
        int bu = w >> 3, h = w & 7;
        int base = bu * 512 + h * 64;
        int c0 = h * 64 + lane32, c1 = c0 + 32;
        float q0 = P.bq[c0], q1 = P.bq[c1];
        #pragma unroll
        for (int p = 0; p < 8; p++) {
            q0 += g_qp[p * QP + base + lane32];
            q1 += g_qp[p * QP + base + lane32 + 32];
        }
        g_q[base + lane32] = q0;
        g_q[base + lane32 + 32] = q1;
        float s = q0 * P.bk[c0] + q1 * P.bk[c1];
        #pragma unroll
        for (int off = 16; off; off >>= 1) s += __shfl_xor_sync(0xffffffffu, s, off);
        if (lane32 == 0) g_qbk[bu * 8 + h] = s;
    }
    grid_bar(nb);

    // ---- S3: Ak = (Wk_h^T q_h)*(1+mk0+mk1)  per-head NT, K=64: 384 tiles ----
    for (int tt = bid; tt < 384; tt += nb) {
        int h = tt / 48, lt = tt % 48;
        int m0 = (lt & 3) * 64, n0 = (lt >> 2) * 64;
        gemm_cp<true>(64, sA, sB, saA, saB,
            [&](int m, int k) { return &g_q[(m0 + m) * 512 + h * 64 + k]; },
            [&](int n, int k) { return &P.Wk[(n0 + n) * 512 + h * 64 + k]; },
            [&](int m, int n, float a) {
                int mg = m0 + m; int b = mg >> 6, u = mg & 63;
                long mi = (long)mg * 768 + n0 + n;
                g_Ak[b * 393216 + (h * 64 + u) * 768 + n0 + n] =
                    a * (1.f + g_mkp[mi] + g_mkp[196608 + mi]);
            });
    }
    grid_bar(nb);

    // ---- S4: score partials, K split x3 (K=256): 384 tiles ----
    for (int tt = bid; tt < 384; tt += nb) {
        int kp = tt >> 7, lt = tt & 127;
        int b = lt >> 5, l2 = lt & 31;
        int m0 = (l2 & 7) * 64, n0 = (l2 >> 3) * 64, kb = kp * 256;
        gemm_cp<true>(256, sA, sB, saA, saB,
            [&](int m, int k) { return &g_Ak[b * 393216 + (m0 + m) * 768 + kb + k]; },
            [&](int n, int k) { return &g_s[(b * 256 + n0 + n) * 768 + kb + k]; },
            [&](int m, int n, float a) {
                g_wp[kp * WP + b * 131072 + (m0 + m) * 256 + n0 + n] = a;
            });
    }
    grid_bar(nb);

    // ---- S5: softmax( (wp0+wp1+wp2+qbk)/8 ) -> g_w ----
    for (int r = wglob; r < 2048; r += nwarp) {
        int b = r >> 9, mg = r & 511;
        int h = mg >> 6, u = mg & 63;
        float qb = g_qbk[(b * 64 + u) * 8 + h];
        long base = (long)b * 131072 + (long)mg * 256;
        float v[8], mx = -1e30f;
        #pragma unroll
        for (int i = 0; i < 8; i++) {
            long idx = base + lane32 + 32 * i;
            v[i] = (g_wp[idx] + g_wp[WP + idx] + g_wp[2 * WP + idx] + qb) * 0.125f;
            mx = fmaxf(mx, v[i]);
        }
        #pragma unroll
        for (int off = 16; off; off >>= 1) mx = fmaxf(mx, __shfl_xor_sync(0xffffffffu, mx, off));
        float sm = 0.f;
        #pragma unroll
        for (int i = 0; i < 8; i++) { v[i] = expf(v[i] - mx); sm += v[i]; }
        #pragma unroll
        for (int off = 16; off; off >>= 1) sm += __shfl_xor_sync(0xffffffffu, sm, off);
        float inv = 1.f / sm;
        #pragma unroll
        for (int i = 0; i < 8; i++) g_w[base + lane32 + 32 * i] = v[i] * inv;
    }
    grid_bar(nb);

    // ---- S6: Tm = (w @ s)*(1+mv0+mv1), per-head remap: 384 tiles, K=256 ----
    for (int tt = bid; tt < 384; tt += nb) {
        int b = tt / 96, lt = tt % 96;
        int m0 = (lt & 7) * 64, n0 = (lt >> 3) * 64;
        gemm_cp<false>(256, sA, sB, saA, saB,
            [&](int m, int k) { return &g_w[b * 131072 + (m0 + m) * 256 + k]; },
            [&](int k, int n) { return &g_s[(b * 256 + k) * 768 + n0 + n]; },
            [&](int m, int n, float a) {
                int mg = m0 + m; int h = mg >> 6, u = mg & 63; int bu = b * 64 + u;
                long mi = (long)bu * 768 + n0 + n;
                g_Tm[(h * 256 + bu) * 768 + n0 + n] =
                    a * (1.f + g_mvp[mi] + g_mvp[196608 + mi]);
            });
    }
    grid_bar(nb);

    // ---- S7: msg partials = Tm_h @ Wv_h, K split x8 (K=96): 256 tiles ----
    for (int tt = bid; tt < 256; tt += nb) {
        int kp = tt >> 5, lt = tt & 31;
        int h = lt >> 2, m0 = (lt & 3) * 64, kb = kp * 96;
        gemm_cp<false>(96, sA, sB, saA, saB,
            [&](int m, int k) { return &g_Tm[(h * 256 + m0 + m) * 768 + kb + k]; },
            [&](int k, int n) { return &P.Wv[(kb + k) * 512 + h * 64 + n]; },
            [&](int m, int n, float a) {
                g_qp[kp * QP + (m0 + m) * 512 + h * 64 + n] = a;
            });
    }
    grid_bar(nb);

    // ---- S7b: msg = (sum(8 partials)+bv)*(1+me0+me1) ----
    for (int i = gt; i < 32768; i += nth) {
        long idx = (long)i * 4;
        int c = (int)(idx & 511);
        float4 acc = ld4(&P.bv[c]);
        #pragma unroll
        for (int p = 0; p < 8; p++) {
            float4 v = ld4(&g_qp[p * QP + idx]);
            acc.x += v.x; acc.y += v.y; acc.z += v.z; acc.w += v.w;
        }
        float4 m0 = ld4(&g_mep[idx]), m1 = ld4(&g_mep[131072 + idx]);
        float4 o;
        o.x = acc.x * (1.f + m0.x + m1.x); o.y = acc.y * (1.f + m0.y + m1.y);
        o.z = acc.z * (1.f + m0.z + m1.z); o.w = acc.w * (1.f + m0.w + m1.w);
        *(float4*)&g_msg[idx] = o;
    }
    grid_bar(nb);

    // ---- S8: out partials = msg @ We, K split x8 (K=64): 384 tiles ----
    for (int tt = bid; tt < 384; tt += nb) {
        int kp = tt / 48, lt = tt % 48;
        int m0 = (lt & 3) * 64, n0 = (lt >> 2) * 64, kb = kp * 64;
        gemm_cp<false>(64, sA, sB, saA, saB,
            [&](int m, int k) { return &g_msg[(m0 + m) * 512 + kb + k]; },
            [&](int k, int n) { return &P.We[(kb + k) * 768 + n0 + n]; },
            [&](int m, int n, float a) {
                g_wp[kp * OP + (m0 + m) * 768 + n0 + n] = a;
            });
    }
    grid_bar(nb);

    // ---- S9: out = recv + (sum(8 partials)+be)*gamma ----
    for (int i = gt; i < 49152; i += nth) {
        long idx = (long)i * 4;
        int c = (int)(idx % 768);
        float4 acc = ld4(&P.be[c]);
        #pragma unroll
        for (int p = 0; p < 8; p++) {
            float4 v = ld4(&g_wp[p * OP + idx]);
            acc.x += v.x; acc.y += v.y; acc.z += v.z; acc.w += v.w;
        }
        float4 ga = ld4(&P.gamma[c]);
        float4 rv = ld4(&P.recv[idx]);
        float4 o;
        o.x = rv.x + acc.x * ga.x; o.y = rv.y + acc.y * ga.y;
        o.z = rv.z + acc.z * ga.z; o.w = rv.w + acc.w * ga.w;
        *(float4*)&P.out[idx] = o;
    }
}

// ---------------- Host launcher ----------------
extern "C" void kernel_launch(void* const* d_in, const int* in_sizes, int n_in,
                              void* d_out, int out_size) {
    (void)in_sizes; (void)n_in; (void)out_size;
    Params P;
    P.recv  = (const float*)d_in[0];
    P.codes = (const float*)d_in[1];
    P.send  = (const float*)d_in[2];
    P.lnrg  = (const float*)d_in[3];
    P.lnrb  = (const float*)d_in[4];
    P.lnsg  = (const float*)d_in[5];
    P.lnsb  = (const float*)d_in[6];
    P.Wq  = (const float*)d_in[7];
    P.bq  = (const float*)d_in[8];
    P.Wmq = (const float*)d_in[9];
    P.Wk  = (const float*)d_in[10];
    P.bk  = (const float*)d_in[11];
    P.Wmk = (const float*)d_in[12];
    P.Wv  = (const float*)d_in[13];
    P.bv  = (const float*)d_in[14];
    P.Wmv = (const float*)d_in[15];
    P.We  = (const float*)d_in[16];
    P.be  = (const float*)d_in[17];
    P.Wme = (const float*)d_in[18];
    P.gamma = (const float*)d_in[19];
    P.out = (float*)d_out;

    int occ = 0;
    cudaOccupancyMaxActiveBlocksPerMultiprocessor(&occ, fused_kernel, TPB, 0);
    if (occ < 1) occ = 1;
    int dev = 0;
    cudaGetDevice(&dev);
    int sms = 0;
    cudaDeviceGetAttribute(&sms, cudaDevAttrMultiProcessorCount, dev);
    if (sms < 1) sms = 1;
    int nb = occ * sms;
    if (nb > 1024) nb = 1024;
    P.nb = nb;

    fused_kernel<<<nb, TPB>>>(P);
}